// round 14
// baseline (speedup 1.0000x reference)
#include <cuda_runtime.h>
#include <cuda_bf16.h>
#include <math.h>
#include <stdint.h>

// Problem constants
#define B_   8
#define S_   4096
#define D_   512
#define P_   128
#define L_   4
#define DF_  2048
#define DH_  256
#define C_   2
#define BS_  (B_*S_)   // 32768 tokens

#define KSPL 8         // split-K factor for kv GEMM
#define KSCH 16        // ksum chunks
#define PLCH 32        // pool chunks

// -------- scratch (device globals) --------
__device__ float g_h[(size_t)BS_*D_];
__device__ float g_v[(size_t)BS_*D_];
__device__ float g_a[(size_t)BS_*D_];
__device__ float g_pq[(size_t)BS_*P_];
__device__ float g_pk[(size_t)BS_*P_];
__device__ float g_kv[(size_t)B_*P_*D_];
__device__ float g_kvp[(size_t)KSPL*B_*P_*D_];
__device__ float g_ksum[B_*P_];
__device__ float g_kspart[KSCH*B_*P_];
__device__ float g_z[BS_];
__device__ float g_pool[B_*D_];
__device__ float g_plpart[PLCH*B_*D_];
__device__ float g_h1[B_*DH_];
__device__ float g_bias3[3*D_];

// bf16 split buffers
__device__ __nv_bfloat16 g_hh[(size_t)BS_*D_];
__device__ __nv_bfloat16 g_hl[(size_t)BS_*D_];
__device__ __nv_bfloat16 g_qkvh[(size_t)BS_*3*D_];
__device__ __nv_bfloat16 g_qkvl[(size_t)BS_*3*D_];
__device__ __nv_bfloat16 g_mh[(size_t)BS_*DF_];
__device__ __nv_bfloat16 g_ml[(size_t)BS_*DF_];
__device__ __nv_bfloat16 g_wth[(size_t)DF_*D_];
__device__ __nv_bfloat16 g_wtl[(size_t)DF_*D_];
__device__ __nv_bfloat16 g_pqh[(size_t)BS_*P_];
__device__ __nv_bfloat16 g_pql[(size_t)BS_*P_];
__device__ __nv_bfloat16 g_kvth[(size_t)B_*D_*P_];
__device__ __nv_bfloat16 g_kvtl[(size_t)B_*D_*P_];

enum { EP_NONE = 0, EP_ELU1 = 1, EP_GELU = 2 };

__device__ __forceinline__ float gelu_f(float x) {
    float x3 = x * x * x;
    float t  = tanhf(0.7978845608028654f * (x + 0.044715f * x3));
    return 0.5f * x * (1.0f + t);
}
__device__ __forceinline__ float epi_apply(float v, int EPI) {
    if (EPI == EP_ELU1) v = (v > 0.f) ? (v + 1.0f) : expf(v);
    if (EPI == EP_GELU) v = gelu_f(v);
    return v;
}

// ================= mma.sync bf16x3 GEMM, 3-stage swizzled pipeline =================
#define TILE_B  (128 * 64)         // 8192 B per operand tile
#define STAGE_B (4 * TILE_B)       // 32768 B
#define NSTAGE  3
#define MMA_SMEM (NSTAGE * STAGE_B)  // 98304

__device__ __forceinline__ uint32_t smem_u32(const void* p) {
    uint32_t a;
    asm("{ .reg .u64 t; cvta.to.shared.u64 t, %1; cvt.u32.u64 %0, t; }" : "=r"(a) : "l"(p));
    return a;
}

#define CP_ASYNC16(dst, src) \
    asm volatile("cp.async.cg.shared.global [%0], [%1], 16;" :: "r"(dst), "l"(src) : "memory")
#define CP_COMMIT() asm volatile("cp.async.commit_group;" ::: "memory")
#define CP_WAIT1()  asm volatile("cp.async.wait_group 1;" ::: "memory")
#define CP_WAIT0()  asm volatile("cp.async.wait_group 0;" ::: "memory")

#define LDSM_X4(r0,r1,r2,r3,addr) \
    asm volatile("ldmatrix.sync.aligned.m8n8.x4.shared.b16 {%0,%1,%2,%3}, [%4];" \
                 : "=r"(r0), "=r"(r1), "=r"(r2), "=r"(r3) : "r"(addr))

__device__ __forceinline__ void mma_bf16(float* c, const uint32_t* a, const uint32_t* b) {
    asm volatile(
        "mma.sync.aligned.m16n8k16.row.col.f32.bf16.bf16.f32 "
        "{%0,%1,%2,%3}, {%4,%5,%6,%7}, {%8,%9}, {%0,%1,%2,%3};"
        : "+f"(c[0]), "+f"(c[1]), "+f"(c[2]), "+f"(c[3])
        : "r"(a[0]), "r"(a[1]), "r"(a[2]), "r"(a[3]), "r"(b[0]), "r"(b[1]));
}

#define SWZ_OFF(r, c) ((uint32_t)((r) * 64 + ((((c) ^ (((r) >> 1) & 3))) << 4)))

// Mainloop body: ALL fragments (Ah, Al, Bh, Bl) prefetched at chunk top;
// three passes run back-to-back with zero mid-chunk loads.
#define MMA_MAINLOOP_BODY(tAh, tAl, tBh, tBl, aBase, cA, sxA, bBase, cB, sxB, acc)   \
    _Pragma("unroll")                                                                \
    for (int ks = 0; ks < 2; ks++) {                                                 \
        const uint32_t acx = (uint32_t)((((ks * 2) + (cA)) ^ (sxA)) << 4);           \
        const uint32_t bcx = (uint32_t)((((ks * 2) + (cB)) ^ (sxB)) << 4);           \
        uint32_t af[4][4], af2[4][4], bhf[4][2], blf[4][2];                          \
        _Pragma("unroll")                                                            \
        for (int mt = 0; mt < 4; mt++)                                               \
            LDSM_X4(af[mt][0], af[mt][1], af[mt][2], af[mt][3],                      \
                    (tAh) + (aBase) + (uint32_t)(mt * 1024) + acx);                  \
        _Pragma("unroll")                                                            \
        for (int mt = 0; mt < 4; mt++)                                               \
            LDSM_X4(af2[mt][0], af2[mt][1], af2[mt][2], af2[mt][3],                  \
                    (tAl) + (aBase) + (uint32_t)(mt * 1024) + acx);                  \
        LDSM_X4(bhf[0][0], bhf[0][1], bhf[1][0], bhf[1][1], (tBh) + (bBase) + bcx);  \
        LDSM_X4(bhf[2][0], bhf[2][1], bhf[3][0], bhf[3][1],                          \
                (tBh) + (bBase) + 1024u + bcx);                                      \
        LDSM_X4(blf[0][0], blf[0][1], blf[1][0], blf[1][1], (tBl) + (bBase) + bcx);  \
        LDSM_X4(blf[2][0], blf[2][1], blf[3][0], blf[3][1],                          \
                (tBl) + (bBase) + 1024u + bcx);                                      \
        _Pragma("unroll")                                                            \
        for (int mt = 0; mt < 4; mt++)                                               \
            _Pragma("unroll")                                                        \
            for (int nt = 0; nt < 4; nt++)                                           \
                mma_bf16(acc[mt][nt], af[mt], bhf[nt]);                              \
        _Pragma("unroll")                                                            \
        for (int mt = 0; mt < 4; mt++)                                               \
            _Pragma("unroll")                                                        \
            for (int nt = 0; nt < 4; nt++)                                           \
                mma_bf16(acc[mt][nt], af[mt], blf[nt]);                              \
        _Pragma("unroll")                                                            \
        for (int mt = 0; mt < 4; mt++)                                               \
            _Pragma("unroll")                                                        \
            for (int nt = 0; nt < 4; nt++)                                           \
                mma_bf16(acc[mt][nt], af2[mt], bhf[nt]);                             \
    }

template <int EPI, bool WF32, bool WSPLIT>
__global__ void __launch_bounds__(256, 2) gemm_mma(
    const __nv_bfloat16* __restrict__ Ah, const __nv_bfloat16* __restrict__ Al, int lda,
    const __nv_bfloat16* __restrict__ Bh, const __nv_bfloat16* __restrict__ Bl,
    const float* __restrict__ bias,
    float* __restrict__ Cf, int ldcf, int cf0,
    __nv_bfloat16* __restrict__ Chi, __nv_bfloat16* __restrict__ Clo, int ldc,
    int M, int N, int K)
{
    extern __shared__ __align__(1024) char smem[];
    const uint32_t sb = smem_u32(smem);

    const int tid  = threadIdx.x;
    const int wid  = tid >> 5;
    const int lane = tid & 31;
    const int wm   = wid & 1;
    const int wn   = wid >> 1;
    const int n0   = blockIdx.x * 128;
    const int m0   = blockIdx.y * 128;

    const __nv_bfloat16* gA[2] = { Ah + (size_t)m0 * lda, Al + (size_t)m0 * lda };
    const __nv_bfloat16* gB[2] = { Bh + (size_t)n0 * K,   Bl + (size_t)n0 * K };

    const int r0 = tid >> 2, cid = tid & 3;
    const uint32_t d0 = SWZ_OFF(r0, cid);
    const uint32_t d1 = SWZ_OFF(r0 + 64, cid);

    auto issue = [&](int slot, int kc) {
        const uint32_t stb = sb + (uint32_t)(slot * STAGE_B);
#pragma unroll
        for (int t = 0; t < 4; t++) {
            const __nv_bfloat16* src = ((t < 2) ? gA[t] : gB[t - 2]) + kc;
            const int ld = (t < 2) ? lda : K;
            uint32_t tb = stb + t * TILE_B;
            CP_ASYNC16(tb + d0, (const void*)(src + (size_t)r0 * ld + cid * 8));
            CP_ASYNC16(tb + d1, (const void*)(src + (size_t)(r0 + 64) * ld + cid * 8));
        }
        CP_COMMIT();
    };

    const int nch = K >> 5;
    float acc[4][4][4] = {};

    issue(0, 0);
    issue(1, 32);

    const int aro = (lane & 7) | (((lane >> 3) & 1) << 3);
    const int cA  = lane >> 4;
    const int sxA = (aro >> 1) & 3;
    const uint32_t aBase = (uint32_t)((wm * 64 + aro) * 64);
    const int bro = (lane & 7) | (((lane >> 4) & 1) << 3);
    const int cB  = (lane >> 3) & 1;
    const int sxB = (bro >> 1) & 3;
    const uint32_t bBase = (uint32_t)((wn * 32 + bro) * 64);

    for (int c = 0; c < nch; c++) {
        if (c + 1 < nch) CP_WAIT1(); else CP_WAIT0();
        __syncthreads();
        if (c + 2 < nch) issue((c + 2) % NSTAGE, (c + 2) << 5);

        const uint32_t stb = sb + (uint32_t)((c % NSTAGE) * STAGE_B);
        const uint32_t tAh = stb, tAl = stb + TILE_B, tBh = stb + 2 * TILE_B, tBl = stb + 3 * TILE_B;

        MMA_MAINLOOP_BODY(tAh, tAl, tBh, tBl, aBase, cA, sxA, bBase, cB, sxB, acc)
    }

#pragma unroll
    for (int mt = 0; mt < 4; mt++) {
        const int gm0 = m0 + wm * 64 + mt * 16 + (lane >> 2);
#pragma unroll
        for (int nt = 0; nt < 4; nt++) {
            const int gn = n0 + wn * 32 + nt * 8 + (lane & 3) * 2;
            const float b0v = bias[gn], b1v = bias[gn + 1];
#pragma unroll
            for (int half = 0; half < 2; half++) {
                const int gm = gm0 + half * 8;
                float v0 = epi_apply(acc[mt][nt][half*2 + 0] + b0v, EPI);
                float v1 = epi_apply(acc[mt][nt][half*2 + 1] + b1v, EPI);
                if (WF32) {
                    if (cf0 == 0 || gn >= cf0)
                        *reinterpret_cast<float2*>(Cf + (size_t)gm * ldcf + (gn - cf0)) = make_float2(v0, v1);
                }
                if (WSPLIT) {
                    __nv_bfloat16 h0 = __float2bfloat16(v0);
                    __nv_bfloat16 h1 = __float2bfloat16(v1);
                    __nv_bfloat16 l0 = __float2bfloat16(v0 - __bfloat162float(h0));
                    __nv_bfloat16 l1 = __float2bfloat16(v1 - __bfloat162float(h1));
                    *reinterpret_cast<__nv_bfloat162*>(Chi + (size_t)gm * ldc + gn) = __nv_bfloat162(h0, h1);
                    *reinterpret_cast<__nv_bfloat162*>(Clo + (size_t)gm * ldc + gn) = __nv_bfloat162(l0, l1);
                }
            }
        }
    }
}

// ===== merged feature-map GEMM: grid.y = 2*BS/128; first half -> pq (+split), second -> pk =====
__global__ void __launch_bounds__(256, 2) gemm_feat(
    const __nv_bfloat16* __restrict__ qkvh, const __nv_bfloat16* __restrict__ qkvl,
    const __nv_bfloat16* __restrict__ Bh, const __nv_bfloat16* __restrict__ Bl,
    const float* __restrict__ bias,
    float* __restrict__ pq, float* __restrict__ pk,
    __nv_bfloat16* __restrict__ pqh, __nv_bfloat16* __restrict__ pql)
{
    extern __shared__ __align__(1024) char smem[];
    const uint32_t sb = smem_u32(smem);

    const int tid  = threadIdx.x;
    const int wid  = tid >> 5;
    const int lane = tid & 31;
    const int wm   = wid & 1;
    const int wn   = wid >> 1;
    const int half_g = (int)(gridDim.y >> 1);
    const bool isQ = ((int)blockIdx.y) < half_g;
    const int m0   = (isQ ? (int)blockIdx.y : (int)blockIdx.y - half_g) * 128;
    const int lda  = 3 * D_;
    const int K    = D_;

    const __nv_bfloat16* gA[2] = { qkvh + (isQ ? 0 : D_) + (size_t)m0 * lda,
                                   qkvl + (isQ ? 0 : D_) + (size_t)m0 * lda };
    const __nv_bfloat16* gB[2] = { Bh, Bl };   // n0 = 0 (N = 128 = one tile)

    const int r0 = tid >> 2, cid = tid & 3;
    const uint32_t d0 = SWZ_OFF(r0, cid);
    const uint32_t d1 = SWZ_OFF(r0 + 64, cid);

    auto issue = [&](int slot, int kc) {
        const uint32_t stb = sb + (uint32_t)(slot * STAGE_B);
#pragma unroll
        for (int t = 0; t < 4; t++) {
            const __nv_bfloat16* src = ((t < 2) ? gA[t] : gB[t - 2]) + kc;
            const int ld = (t < 2) ? lda : K;
            uint32_t tb = stb + t * TILE_B;
            CP_ASYNC16(tb + d0, (const void*)(src + (size_t)r0 * ld + cid * 8));
            CP_ASYNC16(tb + d1, (const void*)(src + (size_t)(r0 + 64) * ld + cid * 8));
        }
        CP_COMMIT();
    };

    const int nch = K >> 5;
    float acc[4][4][4] = {};

    issue(0, 0);
    issue(1, 32);

    const int aro = (lane & 7) | (((lane >> 3) & 1) << 3);
    const int cA  = lane >> 4;
    const int sxA = (aro >> 1) & 3;
    const uint32_t aBase = (uint32_t)((wm * 64 + aro) * 64);
    const int bro = (lane & 7) | (((lane >> 4) & 1) << 3);
    const int cB  = (lane >> 3) & 1;
    const int sxB = (bro >> 1) & 3;
    const uint32_t bBase = (uint32_t)((wn * 32 + bro) * 64);

    for (int c = 0; c < nch; c++) {
        if (c + 1 < nch) CP_WAIT1(); else CP_WAIT0();
        __syncthreads();
        if (c + 2 < nch) issue((c + 2) % NSTAGE, (c + 2) << 5);

        const uint32_t stb = sb + (uint32_t)((c % NSTAGE) * STAGE_B);
        const uint32_t tAh = stb, tAl = stb + TILE_B, tBh = stb + 2 * TILE_B, tBl = stb + 3 * TILE_B;

        MMA_MAINLOOP_BODY(tAh, tAl, tBh, tBl, aBase, cA, sxA, bBase, cB, sxB, acc)
    }

    float* Cf = isQ ? pq : pk;
#pragma unroll
    for (int mt = 0; mt < 4; mt++) {
        const int gm0 = m0 + wm * 64 + mt * 16 + (lane >> 2);
#pragma unroll
        for (int nt = 0; nt < 4; nt++) {
            const int gn = wn * 32 + nt * 8 + (lane & 3) * 2;
            const float b0v = bias[gn], b1v = bias[gn + 1];
#pragma unroll
            for (int half = 0; half < 2; half++) {
                const int gm = gm0 + half * 8;
                float v0 = epi_apply(acc[mt][nt][half*2 + 0] + b0v, EP_ELU1);
                float v1 = epi_apply(acc[mt][nt][half*2 + 1] + b1v, EP_ELU1);
                *reinterpret_cast<float2*>(Cf + (size_t)gm * P_ + gn) = make_float2(v0, v1);
                if (isQ) {
                    __nv_bfloat16 h0 = __float2bfloat16(v0);
                    __nv_bfloat16 h1 = __float2bfloat16(v1);
                    __nv_bfloat16 l0 = __float2bfloat16(v0 - __bfloat162float(h0));
                    __nv_bfloat16 l1 = __float2bfloat16(v1 - __bfloat162float(h1));
                    *reinterpret_cast<__nv_bfloat162*>(pqh + (size_t)gm * P_ + gn) = __nv_bfloat162(h0, h1);
                    *reinterpret_cast<__nv_bfloat162*>(pql + (size_t)gm * P_ + gn) = __nv_bfloat162(l0, l1);
                }
            }
        }
    }
}

// ===== batched zscale GEMM =====
__global__ void __launch_bounds__(256, 2) gemm_zs_mma(
    const __nv_bfloat16* __restrict__ Ah_, const __nv_bfloat16* __restrict__ Al_,
    const __nv_bfloat16* __restrict__ Bh_, const __nv_bfloat16* __restrict__ Bl_,
    const float* __restrict__ zr_,
    __nv_bfloat16* __restrict__ Chi_, __nv_bfloat16* __restrict__ Clo_)
{
    extern __shared__ __align__(1024) char smem[];
    const uint32_t sb = smem_u32(smem);

    const int bz = blockIdx.z;
    const __nv_bfloat16* Ah = Ah_ + (size_t)bz * S_ * P_;
    const __nv_bfloat16* Al = Al_ + (size_t)bz * S_ * P_;
    const __nv_bfloat16* Bh = Bh_ + (size_t)bz * D_ * P_;
    const __nv_bfloat16* Bl = Bl_ + (size_t)bz * D_ * P_;
    const float* zr = zr_ + (size_t)bz * S_;
    __nv_bfloat16* Chi = Chi_ + (size_t)bz * S_ * D_;
    __nv_bfloat16* Clo = Clo_ + (size_t)bz * S_ * D_;

    const int tid  = threadIdx.x;
    const int wid  = tid >> 5;
    const int lane = tid & 31;
    const int wm   = wid & 1;
    const int wn   = wid >> 1;
    const int n0   = blockIdx.x * 128;
    const int m0   = blockIdx.y * 128;

    const __nv_bfloat16* gA[2] = { Ah + (size_t)m0 * P_, Al + (size_t)m0 * P_ };
    const __nv_bfloat16* gB[2] = { Bh + (size_t)n0 * P_, Bl + (size_t)n0 * P_ };

    const int r0 = tid >> 2, cid = tid & 3;
    const uint32_t d0 = SWZ_OFF(r0, cid);
    const uint32_t d1 = SWZ_OFF(r0 + 64, cid);

    auto issue = [&](int slot, int kc) {
        const uint32_t stb = sb + (uint32_t)(slot * STAGE_B);
#pragma unroll
        for (int t = 0; t < 4; t++) {
            const __nv_bfloat16* src = ((t < 2) ? gA[t] : gB[t - 2]) + kc;
            uint32_t tb = stb + t * TILE_B;
            CP_ASYNC16(tb + d0, (const void*)(src + (size_t)r0 * P_ + cid * 8));
            CP_ASYNC16(tb + d1, (const void*)(src + (size_t)(r0 + 64) * P_ + cid * 8));
        }
        CP_COMMIT();
    };

    const int nch = P_ >> 5;
    float acc[4][4][4] = {};

    issue(0, 0);
    issue(1, 32);

    const int aro = (lane & 7) | (((lane >> 3) & 1) << 3);
    const int cA  = lane >> 4;
    const int sxA = (aro >> 1) & 3;
    const uint32_t aBase = (uint32_t)((wm * 64 + aro) * 64);
    const int bro = (lane & 7) | (((lane >> 4) & 1) << 3);
    const int cB  = (lane >> 3) & 1;
    const int sxB = (bro >> 1) & 3;
    const uint32_t bBase = (uint32_t)((wn * 32 + bro) * 64);

    for (int c = 0; c < nch; c++) {
        if (c + 1 < nch) CP_WAIT1(); else CP_WAIT0();
        __syncthreads();
        if (c + 2 < nch) issue((c + 2) % NSTAGE, (c + 2) << 5);

        const uint32_t stb = sb + (uint32_t)((c % NSTAGE) * STAGE_B);
        const uint32_t tAh = stb, tAl = stb + TILE_B, tBh = stb + 2 * TILE_B, tBl = stb + 3 * TILE_B;

        MMA_MAINLOOP_BODY(tAh, tAl, tBh, tBl, aBase, cA, sxA, bBase, cB, sxB, acc)
    }

#pragma unroll
    for (int mt = 0; mt < 4; mt++) {
        const int gm0 = m0 + wm * 64 + mt * 16 + (lane >> 2);
#pragma unroll
        for (int half = 0; half < 2; half++) {
            const int gm = gm0 + half * 8;
            const float zs = 1.0f / (zr[gm] + 1e-6f);
#pragma unroll
            for (int nt = 0; nt < 4; nt++) {
                const int gn = n0 + wn * 32 + nt * 8 + (lane & 3) * 2;
                float v0 = acc[mt][nt][half*2 + 0] * zs;
                float v1 = acc[mt][nt][half*2 + 1] * zs;
                __nv_bfloat16 h0 = __float2bfloat16(v0);
                __nv_bfloat16 h1 = __float2bfloat16(v1);
                __nv_bfloat16 l0 = __float2bfloat16(v0 - __bfloat162float(h0));
                __nv_bfloat16 l1 = __float2bfloat16(v1 - __bfloat162float(h1));
                *reinterpret_cast<__nv_bfloat162*>(Chi + (size_t)gm * D_ + gn) = __nv_bfloat162(h0, h1);
                *reinterpret_cast<__nv_bfloat162*>(Clo + (size_t)gm * D_ + gn) = __nv_bfloat162(l0, l1);
            }
        }
    }
}

// ======== fp32 -> (hi, lo) bf16 split ========
__global__ void split_k(const float* __restrict__ x, __nv_bfloat16* __restrict__ h,
                        __nv_bfloat16* __restrict__ l)
{
    size_t i = ((size_t)blockIdx.x * 256 + threadIdx.x) * 4;
    float4 v = *reinterpret_cast<const float4*>(x + i);
    float vv[4] = {v.x, v.y, v.z, v.w};
    __nv_bfloat16 hh[4], ll[4];
#pragma unroll
    for (int j = 0; j < 4; j++) {
        hh[j] = __float2bfloat16(vv[j]);
        ll[j] = __float2bfloat16(vv[j] - __bfloat162float(hh[j]));
    }
    *reinterpret_cast<__nv_bfloat162*>(h + i)     = __nv_bfloat162(hh[0], hh[1]);
    *reinterpret_cast<__nv_bfloat162*>(h + i + 2) = __nv_bfloat162(hh[2], hh[3]);
    *reinterpret_cast<__nv_bfloat162*>(l + i)     = __nv_bfloat162(ll[0], ll[1]);
    *reinterpret_cast<__nv_bfloat162*>(l + i + 2) = __nv_bfloat162(ll[2], ll[3]);
}

// ======== W[K,N] fp32 -> Wt[N,K] hi/lo bf16 ========
__global__ void tsplit_k(const float* __restrict__ W, __nv_bfloat16* __restrict__ Th,
                         __nv_bfloat16* __restrict__ Tl, int K, int N)
{
    __shared__ float tile[32][33];
    int n0 = blockIdx.x * 32, k0 = blockIdx.y * 32;
    int tx = threadIdx.x, ty = threadIdx.y;
#pragma unroll
    for (int i = 0; i < 4; i++)
        tile[ty + 8 * i][tx] = W[(size_t)(k0 + ty + 8 * i) * N + n0 + tx];
    __syncthreads();
#pragma unroll
    for (int i = 0; i < 4; i++) {
        float v = tile[tx][ty + 8 * i];
        __nv_bfloat16 hi = __float2bfloat16(v);
        __nv_bfloat16 lo = __float2bfloat16(v - __bfloat162float(hi));
        size_t o = (size_t)(n0 + ty + 8 * i) * K + k0 + tx;
        Th[o] = hi;
        Tl[o] = lo;
    }
}

// batched version (kv [P_,D_] -> kvT [D_,P_] per batch)
__global__ void tsplit_b(const float* __restrict__ W_, __nv_bfloat16* __restrict__ Th_,
                         __nv_bfloat16* __restrict__ Tl_, int K, int N)
{
    const int bz = blockIdx.z;
    const float* W = W_ + (size_t)bz * K * N;
    __nv_bfloat16* Th = Th_ + (size_t)bz * N * K;
    __nv_bfloat16* Tl = Tl_ + (size_t)bz * N * K;

    __shared__ float tile[32][33];
    int n0 = blockIdx.x * 32, k0 = blockIdx.y * 32;
    int tx = threadIdx.x, ty = threadIdx.y;
#pragma unroll
    for (int i = 0; i < 4; i++)
        tile[ty + 8 * i][tx] = W[(size_t)(k0 + ty + 8 * i) * N + n0 + tx];
    __syncthreads();
#pragma unroll
    for (int i = 0; i < 4; i++) {
        float v = tile[tx][ty + 8 * i];
        __nv_bfloat16 hi = __float2bfloat16(v);
        __nv_bfloat16 lo = __float2bfloat16(v - __bfloat162float(hi));
        size_t o = (size_t)(n0 + ty + 8 * i) * K + k0 + tx;
        Th[o] = hi;
        Tl[o] = lo;
    }
}

__global__ void pack_bias3(const float* __restrict__ bq, const float* __restrict__ bk,
                           const float* __restrict__ bv, float* __restrict__ b3)
{
    int i = blockIdx.x * 256 + threadIdx.x;
    float v;
    if (i < D_)            v = bq[i];
    else if (i < 2 * D_)   v = bk[i - D_];
    else                   v = bv[i - 2 * D_];
    b3[i] = v;
}

// ======== split-K (deterministic) SIMT TN GEMM ========
#define BM 64
#define BN 64
#define BK 16

__global__ void __launch_bounds__(256) gemm_tn_part(
    const float* __restrict__ A0, const float* __restrict__ B0, float* __restrict__ P0,
    int M, int N, int K, long sA, long sB)
{
    __shared__ __align__(16) float As[BK][BM + 4];
    __shared__ __align__(16) float Bs[BK][BN + 4];

    const int bz = blockIdx.z;
    const int batch  = bz / KSPL;
    const int kslice = bz % KSPL;
    const float* A  = A0 + (long)batch * sA;
    const float* Bp = B0 + (long)batch * sB;
    float* Cp = P0 + ((long)kslice * B_ + batch) * (long)M * N;

    const int kper = K / KSPL;
    const int kbeg = kslice * kper;
    const int kend = kbeg + kper;

    int m0 = blockIdx.y * BM;
    int n0 = blockIdx.x * BN;
    int tid = threadIdx.x;
    int tx = tid & 15, ty = tid >> 4;

    float acc[4][4] = {};

    for (int k0 = kbeg; k0 < kend; k0 += BK) {
#pragma unroll
        for (int e = 0; e < 4; e++) {
            int idx = tid + e * 256;
            int r = idx >> 6, c = idx & 63;
            As[r][c] = A[(long)(k0 + r) * M + (m0 + c)];
            Bs[r][c] = Bp[(long)(k0 + r) * N + (n0 + c)];
        }
        __syncthreads();
#pragma unroll
        for (int kk = 0; kk < BK; kk++) {
            float4 av = *reinterpret_cast<const float4*>(&As[kk][ty * 4]);
            float4 bv = *reinterpret_cast<const float4*>(&Bs[kk][tx * 4]);
            float a4[4] = {av.x, av.y, av.z, av.w};
            float b4[4] = {bv.x, bv.y, bv.z, bv.w};
#pragma unroll
            for (int i = 0; i < 4; i++)
#pragma unroll
                for (int j = 0; j < 4; j++)
                    acc[i][j] = fmaf(a4[i], b4[j], acc[i][j]);
        }
        __syncthreads();
    }

#pragma unroll
    for (int i = 0; i < 4; i++) {
        int m = m0 + ty * 4 + i;
#pragma unroll
        for (int j = 0; j < 4; j++)
            Cp[(long)m * N + (n0 + tx * 4 + j)] = acc[i][j];
    }
}

// reduce kv partials (fixed order)
__global__ void kv_reduce(const float* __restrict__ kvp, float* __restrict__ kv)
{
    size_t i = (size_t)blockIdx.x * 256 + threadIdx.x;
    const size_t stride = (size_t)B_ * P_ * D_;
    float s = 0.f;
#pragma unroll
    for (int ks = 0; ks < KSPL; ks++)
        s += kvp[ks * stride + i];
    kv[i] = s;
}

// -------- embedding + positional --------
__global__ void embed_k(const int* __restrict__ x, const float* __restrict__ emb,
                        const float* __restrict__ pos, float* __restrict__ h)
{
    long idx = (long)blockIdx.x * 256 + threadIdx.x;
    int  d   = (int)(idx & (D_ - 1));
    long tok = idx >> 9;
    int  s   = (int)(tok & (S_ - 1));
    int  xv  = x[tok];
    h[idx] = emb[(long)xv * D_ + d] + pos[(long)s * D_ + d];
}

// -------- ksum two-stage --------
__global__ void ksum_part(const float* __restrict__ pk, float* __restrict__ part)
{
    int b = blockIdx.x;
    int chunk = blockIdx.y;
    int p = threadIdx.x;
    const int rows = S_ / KSCH;
    const float* base = pk + (long)b * S_ * P_ + (long)chunk * rows * P_ + p;
    float s = 0.f;
#pragma unroll 8
    for (int i = 0; i < rows; i++)
        s += base[(long)i * P_];
    part[(chunk * B_ + b) * P_ + p] = s;
}

__global__ void ksum_red(const float* __restrict__ part, float* __restrict__ ks)
{
    int i = blockIdx.x * 256 + threadIdx.x;
    if (i >= B_ * P_) return;
    int b = i / P_, p = i % P_;
    float s = 0.f;
#pragma unroll
    for (int c = 0; c < KSCH; c++)
        s += part[(c * B_ + b) * P_ + p];
    ks[i] = s;
}

// -------- z --------
__global__ void z_k(const float* __restrict__ pq, const float* __restrict__ ks,
                    float* __restrict__ z)
{
    int row  = blockIdx.x * 8 + (threadIdx.x >> 5);
    int lane = threadIdx.x & 31;
    int b = row >> 12;
    const float* pr = pq + (long)row * P_;
    const float* kk = ks + b * P_;
    float s = 0.f;
#pragma unroll
    for (int i = lane; i < P_; i += 32) s += pr[i] * kk[i];
#pragma unroll
    for (int o = 16; o; o >>= 1) s += __shfl_xor_sync(0xffffffffu, s, o);
    if (!lane) z[row] = s;
}

// -------- layernorm, split output --------
__global__ void ln_split_k(const float* __restrict__ in, const float* __restrict__ g,
                           const float* __restrict__ bb,
                           __nv_bfloat16* __restrict__ oh, __nv_bfloat16* __restrict__ ol)
{
    int row = blockIdx.x;
    int t = threadIdx.x;
    const float* x = in + (long)row * D_;
    float v0 = x[t], v1 = x[t + 256];

    float s = v0 + v1;
    __shared__ float red[8];
    __shared__ float red2[8];
#pragma unroll
    for (int o = 16; o; o >>= 1) s += __shfl_xor_sync(0xffffffffu, s, o);
    if ((t & 31) == 0) red[t >> 5] = s;
    __syncthreads();
    float tot = 0.f;
#pragma unroll
    for (int w = 0; w < 8; w++) tot += red[w];
    float mean = tot * (1.0f / 512.0f);

    float d0 = v0 - mean, d1 = v1 - mean;
    float q = d0 * d0 + d1 * d1;
#pragma unroll
    for (int o = 16; o; o >>= 1) q += __shfl_xor_sync(0xffffffffu, q, o);
    if ((t & 31) == 0) red2[t >> 5] = q;
    __syncthreads();
    float tq = 0.f;
#pragma unroll
    for (int w = 0; w < 8; w++) tq += red2[w];
    float inv = rsqrtf(tq * (1.0f / 512.0f) + 1e-5f);

#pragma unroll
    for (int half = 0; half < 2; half++) {
        int d = t + half * 256;
        float dv = (half ? d1 : d0);
        float v = dv * inv * g[d] + bb[d];
        __nv_bfloat16 hi = __float2bfloat16(v);
        __nv_bfloat16 lo = __float2bfloat16(v - __bfloat162float(hi));
        oh[(long)row * D_ + d] = hi;
        ol[(long)row * D_ + d] = lo;
    }
}

// -------- mean pool two-stage --------
__global__ void pool_part(const float* __restrict__ h, float* __restrict__ part)
{
    int b = blockIdx.x;
    int chunk = blockIdx.y;
    int d = threadIdx.x;
    const int rows = S_ / PLCH;
    const float* base = h + (long)b * S_ * D_ + (long)chunk * rows * D_ + d;
    float s = 0.f;
#pragma unroll 8
    for (int i = 0; i < rows; i++)
        s += base[(long)i * D_];
    part[(chunk * B_ + b) * D_ + d] = s;
}

__global__ void pool_red(const float* __restrict__ part, float* __restrict__ pool)
{
    int i = blockIdx.x * 256 + threadIdx.x;
    if (i >= B_ * D_) return;
    int b = i / D_, d = i % D_;
    float s = 0.f;
#pragma unroll
    for (int c = 0; c < PLCH; c++)
        s += part[(c * B_ + b) * D_ + d];
    pool[i] = s * (1.0f / (float)S_);
}

__global__ void head1_k(const float* __restrict__ pool, const float* __restrict__ W,
                        const float* __restrict__ bias, float* __restrict__ h1)
{
    int b = blockIdx.x;
    int j = threadIdx.x;
    const float* p = pool + b * D_;
    float s = bias[j];
    for (int d = 0; d < D_; d++) s += p[d] * W[d * DH_ + j];
    h1[b * DH_ + j] = fmaxf(s, 0.f);
}

__global__ void head2_k(const float* __restrict__ h1, const float* __restrict__ W,
                        const float* __restrict__ bias, float* __restrict__ out)
{
    int i = threadIdx.x;
    int b = i / C_, c = i % C_;
    float s = bias[c];
    for (int d = 0; d < DH_; d++) s += h1[b * DH_ + d] * W[d * C_ + c];
    out[i] = s;
}

// -------- host orchestration --------
static float* sym_addr_f(const void* sym) {
    void* p = nullptr;
    cudaGetSymbolAddress(&p, sym);
    return (float*)p;
}
static __nv_bfloat16* sym_addr_b(const void* sym) {
    void* p = nullptr;
    cudaGetSymbolAddress(&p, sym);
    return (__nv_bfloat16*)p;
}

extern "C" void kernel_launch(void* const* d_in, const int* in_sizes, int n_in,
                              void* d_out, int out_size)
{
    const int*   x    = (const int*)d_in[0];
    const float* emb  = (const float*)d_in[1];
    const float* pos  = (const float*)d_in[2];
    const float* Wq   = (const float*)d_in[3];
    const float* bq   = (const float*)d_in[4];
    const float* Wk   = (const float*)d_in[5];
    const float* bk   = (const float*)d_in[6];
    const float* Wv   = (const float*)d_in[7];
    const float* bv   = (const float*)d_in[8];
    const float* Wf   = (const float*)d_in[9];
    const float* bf   = (const float*)d_in[10];
    const float* Wo   = (const float*)d_in[11];
    const float* bo   = (const float*)d_in[12];
    const float* lng  = (const float*)d_in[13];
    const float* lnb  = (const float*)d_in[14];
    const float* W1   = (const float*)d_in[15];
    const float* b1   = (const float*)d_in[16];
    const float* W2   = (const float*)d_in[17];
    const float* b2   = (const float*)d_in[18];
    const float* Wh1  = (const float*)d_in[19];
    const float* bh1  = (const float*)d_in[20];
    const float* Wh2  = (const float*)d_in[21];
    const float* bh2  = (const float*)d_in[22];
    float* out = (float*)d_out;

    float* h    = sym_addr_f(g_h);
    float* v    = sym_addr_f(g_v);
    float* a    = sym_addr_f(g_a);
    float* pq   = sym_addr_f(g_pq);
    float* pk   = sym_addr_f(g_pk);
    float* kv   = sym_addr_f(g_kv);
    float* kvp  = sym_addr_f(g_kvp);
    float* ksum = sym_addr_f(g_ksum);
    float* ksp  = sym_addr_f(g_kspart);
    float* z    = sym_addr_f(g_z);
    float* pool = sym_addr_f(g_pool);
    float* plp  = sym_addr_f(g_plpart);
    float* h1   = sym_addr_f(g_h1);
    float* b3   = sym_addr_f(g_bias3);

    __nv_bfloat16* hh   = sym_addr_b(g_hh);
    __nv_bfloat16* hl   = sym_addr_b(g_hl);
    __nv_bfloat16* qkvh = sym_addr_b(g_qkvh);
    __nv_bfloat16* qkvl = sym_addr_b(g_qkvl);
    __nv_bfloat16* mh   = sym_addr_b(g_mh);
    __nv_bfloat16* ml   = sym_addr_b(g_ml);
    __nv_bfloat16* wth  = sym_addr_b(g_wth);
    __nv_bfloat16* wtl  = sym_addr_b(g_wtl);
    __nv_bfloat16* pqh  = sym_addr_b(g_pqh);
    __nv_bfloat16* pql  = sym_addr_b(g_pql);
    __nv_bfloat16* kvth = sym_addr_b(g_kvth);
    __nv_bfloat16* kvtl = sym_addr_b(g_kvtl);

    cudaFuncSetAttribute(gemm_mma<EP_NONE, true,  true >, cudaFuncAttributeMaxDynamicSharedMemorySize, MMA_SMEM);
    cudaFuncSetAttribute(gemm_mma<EP_NONE, true,  false>, cudaFuncAttributeMaxDynamicSharedMemorySize, MMA_SMEM);
    cudaFuncSetAttribute(gemm_mma<EP_NONE, false, true >, cudaFuncAttributeMaxDynamicSharedMemorySize, MMA_SMEM);
    cudaFuncSetAttribute(gemm_mma<EP_GELU, false, true >, cudaFuncAttributeMaxDynamicSharedMemorySize, MMA_SMEM);
    cudaFuncSetAttribute(gemm_feat, cudaFuncAttributeMaxDynamicSharedMemorySize, MMA_SMEM);
    cudaFuncSetAttribute(gemm_zs_mma, cudaFuncAttributeMaxDynamicSharedMemorySize, MMA_SMEM);

    embed_k<<<(BS_ * D_) / 256, 256>>>(x, emb, pos, h);
    split_k<<<(BS_ * D_) / 1024, 256>>>(h, hh, hl);

    dim3 tsD(32, 8);

    for (int l = 0; l < L_; l++) {
        const float* wq = Wq + (long)l * D_ * D_;
        const float* wk = Wk + (long)l * D_ * D_;
        const float* wv = Wv + (long)l * D_ * D_;
        const float* wf = Wf + (long)l * D_ * P_;
        const float* wo = Wo + (long)l * D_ * D_;
        const float* w1 = W1 + (long)l * D_ * DF_;
        const float* w2 = W2 + (long)l * DF_ * D_;

        // ---- fused QKV: N = 1536 ----
        pack_bias3<<<6, 256>>>(bq + l * D_, bk + l * D_, bv + l * D_, b3);
        tsplit_k<<<dim3(D_ / 32, D_ / 32), tsD>>>(wq, wth,                    wtl,                    D_, D_);
        tsplit_k<<<dim3(D_ / 32, D_ / 32), tsD>>>(wk, wth + (size_t)D_ * D_,  wtl + (size_t)D_ * D_,  D_, D_);
        tsplit_k<<<dim3(D_ / 32, D_ / 32), tsD>>>(wv, wth + (size_t)2*D_*D_,  wtl + (size_t)2*D_*D_,  D_, D_);
        dim3 gQKV(3 * D_ / 128, BS_ / 128);
        gemm_mma<EP_NONE, true, true><<<gQKV, 256, MMA_SMEM>>>(
            hh, hl, D_, wth, wtl, b3,
            v, D_, 2 * D_,
            qkvh, qkvl, 3 * D_, BS_, 3 * D_, D_);

        // ---- feature maps (merged pq + pk launch) ----
        tsplit_k<<<dim3(P_ / 32, D_ / 32), tsD>>>(wf, wth, wtl, D_, P_);
        gemm_feat<<<dim3(1, 2 * BS_ / 128), 256, MMA_SMEM>>>(
            qkvh, qkvl, wth, wtl, bf + l * P_, pq, pk, pqh, pql);

        // ---- linear attention core ----
        ksum_part<<<dim3(B_, KSCH), P_>>>(pk, ksp);
        ksum_red<<<(B_ * P_ + 255) / 256, 256>>>(ksp, ksum);
        dim3 gKV(D_ / BN, P_ / BM, B_ * KSPL);
        gemm_tn_part<<<gKV, 256>>>(pk, v, kvp, P_, D_, S_,
                                   (long)S_ * P_, (long)S_ * D_);
        kv_reduce<<<(B_ * P_ * D_) / 256, 256>>>(kvp, kv);
        z_k<<<BS_ / 8, 256>>>(pq, ksum, z);
        tsplit_b<<<dim3(D_ / 32, P_ / 32, B_), tsD>>>(kv, kvth, kvtl, P_, D_);
        dim3 gZS(D_ / 128, S_ / 128, B_);
        gemm_zs_mma<<<gZS, 256, MMA_SMEM>>>(pqh, pql, kvth, kvtl, z, hh, hl);

        // ---- Wo ----
        tsplit_k<<<dim3(D_ / 32, D_ / 32), tsD>>>(wo, wth, wtl, D_, D_);
        dim3 gDD(D_ / 128, BS_ / 128);
        gemm_mma<EP_NONE, true, false><<<gDD, 256, MMA_SMEM>>>(
            hh, hl, D_, wth, wtl, bo + l * D_,
            a, D_, 0, nullptr, nullptr, 0, BS_, D_, D_);

        ln_split_k<<<BS_, 256>>>(a, lng + l * D_, lnb + l * D_, hh, hl);

        // ---- MLP ----
        tsplit_k<<<dim3(DF_ / 32, D_ / 32), tsD>>>(w1, wth, wtl, D_, DF_);
        dim3 gW1(DF_ / 128, BS_ / 128);
        gemm_mma<EP_GELU, false, true><<<gW1, 256, MMA_SMEM>>>(
            hh, hl, D_, wth, wtl, b1 + l * DF_,
            nullptr, 0, 0, mh, ml, DF_, BS_, DF_, D_);
        tsplit_k<<<dim3(D_ / 32, DF_ / 32), tsD>>>(w2, wth, wtl, DF_, D_);
        if (l == L_ - 1) {
            gemm_mma<EP_NONE, true, true><<<gDD, 256, MMA_SMEM>>>(
                mh, ml, DF_, wth, wtl, b2 + l * D_,
                h, D_, 0, hh, hl, D_, BS_, D_, DF_);
        } else {
            gemm_mma<EP_NONE, false, true><<<gDD, 256, MMA_SMEM>>>(
                mh, ml, DF_, wth, wtl, b2 + l * D_,
                nullptr, 0, 0, hh, hl, D_, BS_, D_, DF_);
        }
    }

    pool_part<<<dim3(B_, PLCH), D_>>>(h, plp);
    pool_red<<<(B_ * D_ + 255) / 256, 256>>>(plp, pool);
    head1_k<<<B_, DH_>>>(pool, Wh1, bh1, h1);
    head2_k<<<1, B_ * C_>>>(h1, Wh2, bh2, out);
}

// round 15
// speedup vs baseline: 1.0124x; 1.0124x over previous
#include <cuda_runtime.h>
#include <cuda_bf16.h>
#include <math.h>
#include <stdint.h>

// Problem constants
#define B_   8
#define S_   4096
#define D_   512
#define P_   128
#define L_   4
#define DF_  2048
#define DH_  256
#define C_   2
#define BS_  (B_*S_)   // 32768 tokens

#define KSPL 8         // split-K factor for kv GEMM
#define KSCH 16        // ksum chunks
#define PLCH 32        // pool chunks

// -------- scratch (device globals) --------
__device__ float g_h[(size_t)BS_*D_];
__device__ float g_v[(size_t)BS_*D_];
__device__ float g_a[(size_t)BS_*D_];
__device__ float g_pq[(size_t)BS_*P_];
__device__ float g_pk[(size_t)BS_*P_];
__device__ float g_kv[(size_t)B_*P_*D_];
__device__ float g_kvp[(size_t)KSPL*B_*P_*D_];
__device__ float g_ksum[B_*P_];
__device__ float g_kspart[KSCH*B_*P_];
__device__ float g_z[BS_];
__device__ float g_pool[B_*D_];
__device__ float g_plpart[PLCH*B_*D_];
__device__ float g_h1[B_*DH_];
__device__ float g_bias3[L_*3*D_];

// bf16 split buffers (activations)
__device__ __nv_bfloat16 g_hh[(size_t)BS_*D_];
__device__ __nv_bfloat16 g_hl[(size_t)BS_*D_];
__device__ __nv_bfloat16 g_qkvh[(size_t)BS_*3*D_];
__device__ __nv_bfloat16 g_qkvl[(size_t)BS_*3*D_];
__device__ __nv_bfloat16 g_mh[(size_t)BS_*DF_];
__device__ __nv_bfloat16 g_ml[(size_t)BS_*DF_];
__device__ __nv_bfloat16 g_pqh[(size_t)BS_*P_];
__device__ __nv_bfloat16 g_pql[(size_t)BS_*P_];
__device__ __nv_bfloat16 g_kvth[(size_t)B_*D_*P_];
__device__ __nv_bfloat16 g_kvtl[(size_t)B_*D_*P_];

// bf16 split weights (all layers, transposed [N,K] K-major), hoisted
__device__ __nv_bfloat16 g_wqkvh[(size_t)L_*3*D_*D_];
__device__ __nv_bfloat16 g_wqkvl[(size_t)L_*3*D_*D_];
__device__ __nv_bfloat16 g_wfh[(size_t)L_*P_*D_];
__device__ __nv_bfloat16 g_wfl[(size_t)L_*P_*D_];
__device__ __nv_bfloat16 g_woh[(size_t)L_*D_*D_];
__device__ __nv_bfloat16 g_wol[(size_t)L_*D_*D_];
__device__ __nv_bfloat16 g_w1h[(size_t)L_*DF_*D_];
__device__ __nv_bfloat16 g_w1l[(size_t)L_*DF_*D_];
__device__ __nv_bfloat16 g_w2h[(size_t)L_*D_*DF_];
__device__ __nv_bfloat16 g_w2l[(size_t)L_*D_*DF_];

enum { EP_NONE = 0, EP_ELU1 = 1, EP_GELU = 2 };

__device__ __forceinline__ float gelu_f(float x) {
    float x3 = x * x * x;
    float t  = tanhf(0.7978845608028654f * (x + 0.044715f * x3));
    return 0.5f * x * (1.0f + t);
}
__device__ __forceinline__ float epi_apply(float v, int EPI) {
    if (EPI == EP_ELU1) v = (v > 0.f) ? (v + 1.0f) : expf(v);
    if (EPI == EP_GELU) v = gelu_f(v);
    return v;
}

// ================= mma.sync bf16x3 GEMM, 3-stage swizzled pipeline =================
#define TILE_B  (128 * 64)         // 8192 B per operand tile
#define STAGE_B (4 * TILE_B)       // 32768 B
#define NSTAGE  3
#define MMA_SMEM (NSTAGE * STAGE_B)  // 98304

__device__ __forceinline__ uint32_t smem_u32(const void* p) {
    uint32_t a;
    asm("{ .reg .u64 t; cvta.to.shared.u64 t, %1; cvt.u32.u64 %0, t; }" : "=r"(a) : "l"(p));
    return a;
}

#define CP_ASYNC16(dst, src) \
    asm volatile("cp.async.cg.shared.global [%0], [%1], 16;" :: "r"(dst), "l"(src) : "memory")
#define CP_COMMIT() asm volatile("cp.async.commit_group;" ::: "memory")
#define CP_WAIT1()  asm volatile("cp.async.wait_group 1;" ::: "memory")
#define CP_WAIT0()  asm volatile("cp.async.wait_group 0;" ::: "memory")

#define LDSM_X4(r0,r1,r2,r3,addr) \
    asm volatile("ldmatrix.sync.aligned.m8n8.x4.shared.b16 {%0,%1,%2,%3}, [%4];" \
                 : "=r"(r0), "=r"(r1), "=r"(r2), "=r"(r3) : "r"(addr))

__device__ __forceinline__ void mma_bf16(float* c, const uint32_t* a, const uint32_t* b) {
    asm volatile(
        "mma.sync.aligned.m16n8k16.row.col.f32.bf16.bf16.f32 "
        "{%0,%1,%2,%3}, {%4,%5,%6,%7}, {%8,%9}, {%0,%1,%2,%3};"
        : "+f"(c[0]), "+f"(c[1]), "+f"(c[2]), "+f"(c[3])
        : "r"(a[0]), "r"(a[1]), "r"(a[2]), "r"(a[3]), "r"(b[0]), "r"(b[1]));
}

#define SWZ_OFF(r, c) ((uint32_t)((r) * 64 + ((((c) ^ (((r) >> 1) & 3))) << 4)))

// R13-proven mainloop body (pass-major; af reloaded from Al mid-chunk).
#define MMA_MAINLOOP_BODY(tAh, tAl, tBh, tBl, aBase, cA, sxA, bBase, cB, sxB, acc)   \
    _Pragma("unroll")                                                                \
    for (int ks = 0; ks < 2; ks++) {                                                 \
        const uint32_t acx = (uint32_t)((((ks * 2) + (cA)) ^ (sxA)) << 4);           \
        const uint32_t bcx = (uint32_t)((((ks * 2) + (cB)) ^ (sxB)) << 4);           \
        uint32_t af[4][4], bhf[4][2], blf[4][2];                                     \
        _Pragma("unroll")                                                            \
        for (int mt = 0; mt < 4; mt++)                                               \
            LDSM_X4(af[mt][0], af[mt][1], af[mt][2], af[mt][3],                      \
                    (tAh) + (aBase) + (uint32_t)(mt * 1024) + acx);                  \
        LDSM_X4(bhf[0][0], bhf[0][1], bhf[1][0], bhf[1][1], (tBh) + (bBase) + bcx);  \
        LDSM_X4(bhf[2][0], bhf[2][1], bhf[3][0], bhf[3][1],                          \
                (tBh) + (bBase) + 1024u + bcx);                                      \
        LDSM_X4(blf[0][0], blf[0][1], blf[1][0], blf[1][1], (tBl) + (bBase) + bcx);  \
        LDSM_X4(blf[2][0], blf[2][1], blf[3][0], blf[3][1],                          \
                (tBl) + (bBase) + 1024u + bcx);                                      \
        _Pragma("unroll")                                                            \
        for (int mt = 0; mt < 4; mt++)                                               \
            _Pragma("unroll")                                                        \
            for (int nt = 0; nt < 4; nt++)                                           \
                mma_bf16(acc[mt][nt], af[mt], bhf[nt]);                              \
        _Pragma("unroll")                                                            \
        for (int mt = 0; mt < 4; mt++)                                               \
            _Pragma("unroll")                                                        \
            for (int nt = 0; nt < 4; nt++)                                           \
                mma_bf16(acc[mt][nt], af[mt], blf[nt]);                              \
        _Pragma("unroll")                                                            \
        for (int mt = 0; mt < 4; mt++)                                               \
            LDSM_X4(af[mt][0], af[mt][1], af[mt][2], af[mt][3],                      \
                    (tAl) + (aBase) + (uint32_t)(mt * 1024) + acx);                  \
        _Pragma("unroll")                                                            \
        for (int mt = 0; mt < 4; mt++)                                               \
            _Pragma("unroll")                                                        \
            for (int nt = 0; nt < 4; nt++)                                           \
                mma_bf16(acc[mt][nt], af[mt], bhf[nt]);                              \
    }

template <int EPI, bool WF32, bool WSPLIT>
__global__ void __launch_bounds__(256, 2) gemm_mma(
    const __nv_bfloat16* __restrict__ Ah, const __nv_bfloat16* __restrict__ Al, int lda,
    const __nv_bfloat16* __restrict__ Bh, const __nv_bfloat16* __restrict__ Bl,
    const float* __restrict__ bias,
    float* __restrict__ Cf, int ldcf, int cf0,
    __nv_bfloat16* __restrict__ Chi, __nv_bfloat16* __restrict__ Clo, int ldc,
    int M, int N, int K)
{
    extern __shared__ __align__(1024) char smem[];
    const uint32_t sb = smem_u32(smem);

    const int tid  = threadIdx.x;
    const int wid  = tid >> 5;
    const int lane = tid & 31;
    const int wm   = wid & 1;
    const int wn   = wid >> 1;
    const int n0   = blockIdx.x * 128;
    const int m0   = blockIdx.y * 128;

    const __nv_bfloat16* gA[2] = { Ah + (size_t)m0 * lda, Al + (size_t)m0 * lda };
    const __nv_bfloat16* gB[2] = { Bh + (size_t)n0 * K,   Bl + (size_t)n0 * K };

    const int r0 = tid >> 2, cid = tid & 3;
    const uint32_t d0 = SWZ_OFF(r0, cid);
    const uint32_t d1 = SWZ_OFF(r0 + 64, cid);

    auto issue = [&](int slot, int kc) {
        const uint32_t stb = sb + (uint32_t)(slot * STAGE_B);
#pragma unroll
        for (int t = 0; t < 4; t++) {
            const __nv_bfloat16* src = ((t < 2) ? gA[t] : gB[t - 2]) + kc;
            const int ld = (t < 2) ? lda : K;
            uint32_t tb = stb + t * TILE_B;
            CP_ASYNC16(tb + d0, (const void*)(src + (size_t)r0 * ld + cid * 8));
            CP_ASYNC16(tb + d1, (const void*)(src + (size_t)(r0 + 64) * ld + cid * 8));
        }
        CP_COMMIT();
    };

    const int nch = K >> 5;
    float acc[4][4][4] = {};

    issue(0, 0);
    issue(1, 32);

    const int aro = (lane & 7) | (((lane >> 3) & 1) << 3);
    const int cA  = lane >> 4;
    const int sxA = (aro >> 1) & 3;
    const uint32_t aBase = (uint32_t)((wm * 64 + aro) * 64);
    const int bro = (lane & 7) | (((lane >> 4) & 1) << 3);
    const int cB  = (lane >> 3) & 1;
    const int sxB = (bro >> 1) & 3;
    const uint32_t bBase = (uint32_t)((wn * 32 + bro) * 64);

    for (int c = 0; c < nch; c++) {
        if (c + 1 < nch) CP_WAIT1(); else CP_WAIT0();
        __syncthreads();
        if (c + 2 < nch) issue((c + 2) % NSTAGE, (c + 2) << 5);

        const uint32_t stb = sb + (uint32_t)((c % NSTAGE) * STAGE_B);
        const uint32_t tAh = stb, tAl = stb + TILE_B, tBh = stb + 2 * TILE_B, tBl = stb + 3 * TILE_B;

        MMA_MAINLOOP_BODY(tAh, tAl, tBh, tBl, aBase, cA, sxA, bBase, cB, sxB, acc)
    }

#pragma unroll
    for (int mt = 0; mt < 4; mt++) {
        const int gm0 = m0 + wm * 64 + mt * 16 + (lane >> 2);
#pragma unroll
        for (int nt = 0; nt < 4; nt++) {
            const int gn = n0 + wn * 32 + nt * 8 + (lane & 3) * 2;
            const float b0v = bias[gn], b1v = bias[gn + 1];
#pragma unroll
            for (int half = 0; half < 2; half++) {
                const int gm = gm0 + half * 8;
                float v0 = epi_apply(acc[mt][nt][half*2 + 0] + b0v, EPI);
                float v1 = epi_apply(acc[mt][nt][half*2 + 1] + b1v, EPI);
                if (WF32) {
                    if (cf0 == 0 || gn >= cf0)
                        *reinterpret_cast<float2*>(Cf + (size_t)gm * ldcf + (gn - cf0)) = make_float2(v0, v1);
                }
                if (WSPLIT) {
                    __nv_bfloat16 h0 = __float2bfloat16(v0);
                    __nv_bfloat16 h1 = __float2bfloat16(v1);
                    __nv_bfloat16 l0 = __float2bfloat16(v0 - __bfloat162float(h0));
                    __nv_bfloat16 l1 = __float2bfloat16(v1 - __bfloat162float(h1));
                    *reinterpret_cast<__nv_bfloat162*>(Chi + (size_t)gm * ldc + gn) = __nv_bfloat162(h0, h1);
                    *reinterpret_cast<__nv_bfloat162*>(Clo + (size_t)gm * ldc + gn) = __nv_bfloat162(l0, l1);
                }
            }
        }
    }
}

// ===== merged feature-map GEMM: grid.y = 2*BS/128; first half -> pq (+split), second -> pk =====
__global__ void __launch_bounds__(256, 2) gemm_feat(
    const __nv_bfloat16* __restrict__ qkvh, const __nv_bfloat16* __restrict__ qkvl,
    const __nv_bfloat16* __restrict__ Bh, const __nv_bfloat16* __restrict__ Bl,
    const float* __restrict__ bias,
    float* __restrict__ pq, float* __restrict__ pk,
    __nv_bfloat16* __restrict__ pqh, __nv_bfloat16* __restrict__ pql)
{
    extern __shared__ __align__(1024) char smem[];
    const uint32_t sb = smem_u32(smem);

    const int tid  = threadIdx.x;
    const int wid  = tid >> 5;
    const int lane = tid & 31;
    const int wm   = wid & 1;
    const int wn   = wid >> 1;
    const int half_g = (int)(gridDim.y >> 1);
    const bool isQ = ((int)blockIdx.y) < half_g;
    const int m0   = (isQ ? (int)blockIdx.y : (int)blockIdx.y - half_g) * 128;
    const int lda  = 3 * D_;
    const int K    = D_;

    const __nv_bfloat16* gA[2] = { qkvh + (isQ ? 0 : D_) + (size_t)m0 * lda,
                                   qkvl + (isQ ? 0 : D_) + (size_t)m0 * lda };
    const __nv_bfloat16* gB[2] = { Bh, Bl };

    const int r0 = tid >> 2, cid = tid & 3;
    const uint32_t d0 = SWZ_OFF(r0, cid);
    const uint32_t d1 = SWZ_OFF(r0 + 64, cid);

    auto issue = [&](int slot, int kc) {
        const uint32_t stb = sb + (uint32_t)(slot * STAGE_B);
#pragma unroll
        for (int t = 0; t < 4; t++) {
            const __nv_bfloat16* src = ((t < 2) ? gA[t] : gB[t - 2]) + kc;
            const int ld = (t < 2) ? lda : K;
            uint32_t tb = stb + t * TILE_B;
            CP_ASYNC16(tb + d0, (const void*)(src + (size_t)r0 * ld + cid * 8));
            CP_ASYNC16(tb + d1, (const void*)(src + (size_t)(r0 + 64) * ld + cid * 8));
        }
        CP_COMMIT();
    };

    const int nch = K >> 5;
    float acc[4][4][4] = {};

    issue(0, 0);
    issue(1, 32);

    const int aro = (lane & 7) | (((lane >> 3) & 1) << 3);
    const int cA  = lane >> 4;
    const int sxA = (aro >> 1) & 3;
    const uint32_t aBase = (uint32_t)((wm * 64 + aro) * 64);
    const int bro = (lane & 7) | (((lane >> 4) & 1) << 3);
    const int cB  = (lane >> 3) & 1;
    const int sxB = (bro >> 1) & 3;
    const uint32_t bBase = (uint32_t)((wn * 32 + bro) * 64);

    for (int c = 0; c < nch; c++) {
        if (c + 1 < nch) CP_WAIT1(); else CP_WAIT0();
        __syncthreads();
        if (c + 2 < nch) issue((c + 2) % NSTAGE, (c + 2) << 5);

        const uint32_t stb = sb + (uint32_t)((c % NSTAGE) * STAGE_B);
        const uint32_t tAh = stb, tAl = stb + TILE_B, tBh = stb + 2 * TILE_B, tBl = stb + 3 * TILE_B;

        MMA_MAINLOOP_BODY(tAh, tAl, tBh, tBl, aBase, cA, sxA, bBase, cB, sxB, acc)
    }

    float* Cf = isQ ? pq : pk;
#pragma unroll
    for (int mt = 0; mt < 4; mt++) {
        const int gm0 = m0 + wm * 64 + mt * 16 + (lane >> 2);
#pragma unroll
        for (int nt = 0; nt < 4; nt++) {
            const int gn = wn * 32 + nt * 8 + (lane & 3) * 2;
            const float b0v = bias[gn], b1v = bias[gn + 1];
#pragma unroll
            for (int half = 0; half < 2; half++) {
                const int gm = gm0 + half * 8;
                float v0 = epi_apply(acc[mt][nt][half*2 + 0] + b0v, EP_ELU1);
                float v1 = epi_apply(acc[mt][nt][half*2 + 1] + b1v, EP_ELU1);
                *reinterpret_cast<float2*>(Cf + (size_t)gm * P_ + gn) = make_float2(v0, v1);
                if (isQ) {
                    __nv_bfloat16 h0 = __float2bfloat16(v0);
                    __nv_bfloat16 h1 = __float2bfloat16(v1);
                    __nv_bfloat16 l0 = __float2bfloat16(v0 - __bfloat162float(h0));
                    __nv_bfloat16 l1 = __float2bfloat16(v1 - __bfloat162float(h1));
                    *reinterpret_cast<__nv_bfloat162*>(pqh + (size_t)gm * P_ + gn) = __nv_bfloat162(h0, h1);
                    *reinterpret_cast<__nv_bfloat162*>(pql + (size_t)gm * P_ + gn) = __nv_bfloat162(l0, l1);
                }
            }
        }
    }
}

// ===== batched zscale GEMM =====
__global__ void __launch_bounds__(256, 2) gemm_zs_mma(
    const __nv_bfloat16* __restrict__ Ah_, const __nv_bfloat16* __restrict__ Al_,
    const __nv_bfloat16* __restrict__ Bh_, const __nv_bfloat16* __restrict__ Bl_,
    const float* __restrict__ zr_,
    __nv_bfloat16* __restrict__ Chi_, __nv_bfloat16* __restrict__ Clo_)
{
    extern __shared__ __align__(1024) char smem[];
    const uint32_t sb = smem_u32(smem);

    const int bz = blockIdx.z;
    const __nv_bfloat16* Ah = Ah_ + (size_t)bz * S_ * P_;
    const __nv_bfloat16* Al = Al_ + (size_t)bz * S_ * P_;
    const __nv_bfloat16* Bh = Bh_ + (size_t)bz * D_ * P_;
    const __nv_bfloat16* Bl = Bl_ + (size_t)bz * D_ * P_;
    const float* zr = zr_ + (size_t)bz * S_;
    __nv_bfloat16* Chi = Chi_ + (size_t)bz * S_ * D_;
    __nv_bfloat16* Clo = Clo_ + (size_t)bz * S_ * D_;

    const int tid  = threadIdx.x;
    const int wid  = tid >> 5;
    const int lane = tid & 31;
    const int wm   = wid & 1;
    const int wn   = wid >> 1;
    const int n0   = blockIdx.x * 128;
    const int m0   = blockIdx.y * 128;

    const __nv_bfloat16* gA[2] = { Ah + (size_t)m0 * P_, Al + (size_t)m0 * P_ };
    const __nv_bfloat16* gB[2] = { Bh + (size_t)n0 * P_, Bl + (size_t)n0 * P_ };

    const int r0 = tid >> 2, cid = tid & 3;
    const uint32_t d0 = SWZ_OFF(r0, cid);
    const uint32_t d1 = SWZ_OFF(r0 + 64, cid);

    auto issue = [&](int slot, int kc) {
        const uint32_t stb = sb + (uint32_t)(slot * STAGE_B);
#pragma unroll
        for (int t = 0; t < 4; t++) {
            const __nv_bfloat16* src = ((t < 2) ? gA[t] : gB[t - 2]) + kc;
            uint32_t tb = stb + t * TILE_B;
            CP_ASYNC16(tb + d0, (const void*)(src + (size_t)r0 * P_ + cid * 8));
            CP_ASYNC16(tb + d1, (const void*)(src + (size_t)(r0 + 64) * P_ + cid * 8));
        }
        CP_COMMIT();
    };

    const int nch = P_ >> 5;
    float acc[4][4][4] = {};

    issue(0, 0);
    issue(1, 32);

    const int aro = (lane & 7) | (((lane >> 3) & 1) << 3);
    const int cA  = lane >> 4;
    const int sxA = (aro >> 1) & 3;
    const uint32_t aBase = (uint32_t)((wm * 64 + aro) * 64);
    const int bro = (lane & 7) | (((lane >> 4) & 1) << 3);
    const int cB  = (lane >> 3) & 1;
    const int sxB = (bro >> 1) & 3;
    const uint32_t bBase = (uint32_t)((wn * 32 + bro) * 64);

    for (int c = 0; c < nch; c++) {
        if (c + 1 < nch) CP_WAIT1(); else CP_WAIT0();
        __syncthreads();
        if (c + 2 < nch) issue((c + 2) % NSTAGE, (c + 2) << 5);

        const uint32_t stb = sb + (uint32_t)((c % NSTAGE) * STAGE_B);
        const uint32_t tAh = stb, tAl = stb + TILE_B, tBh = stb + 2 * TILE_B, tBl = stb + 3 * TILE_B;

        MMA_MAINLOOP_BODY(tAh, tAl, tBh, tBl, aBase, cA, sxA, bBase, cB, sxB, acc)
    }

#pragma unroll
    for (int mt = 0; mt < 4; mt++) {
        const int gm0 = m0 + wm * 64 + mt * 16 + (lane >> 2);
#pragma unroll
        for (int half = 0; half < 2; half++) {
            const int gm = gm0 + half * 8;
            const float zs = 1.0f / (zr[gm] + 1e-6f);
#pragma unroll
            for (int nt = 0; nt < 4; nt++) {
                const int gn = n0 + wn * 32 + nt * 8 + (lane & 3) * 2;
                float v0 = acc[mt][nt][half*2 + 0] * zs;
                float v1 = acc[mt][nt][half*2 + 1] * zs;
                __nv_bfloat16 h0 = __float2bfloat16(v0);
                __nv_bfloat16 h1 = __float2bfloat16(v1);
                __nv_bfloat16 l0 = __float2bfloat16(v0 - __bfloat162float(h0));
                __nv_bfloat16 l1 = __float2bfloat16(v1 - __bfloat162float(h1));
                *reinterpret_cast<__nv_bfloat162*>(Chi + (size_t)gm * D_ + gn) = __nv_bfloat162(h0, h1);
                *reinterpret_cast<__nv_bfloat162*>(Clo + (size_t)gm * D_ + gn) = __nv_bfloat162(l0, l1);
            }
        }
    }
}

// ======== fp32 -> (hi, lo) bf16 split ========
__global__ void split_k(const float* __restrict__ x, __nv_bfloat16* __restrict__ h,
                        __nv_bfloat16* __restrict__ l)
{
    size_t i = ((size_t)blockIdx.x * 256 + threadIdx.x) * 4;
    float4 v = *reinterpret_cast<const float4*>(x + i);
    float vv[4] = {v.x, v.y, v.z, v.w};
    __nv_bfloat16 hh[4], ll[4];
#pragma unroll
    for (int j = 0; j < 4; j++) {
        hh[j] = __float2bfloat16(vv[j]);
        ll[j] = __float2bfloat16(vv[j] - __bfloat162float(hh[j]));
    }
    *reinterpret_cast<__nv_bfloat162*>(h + i)     = __nv_bfloat162(hh[0], hh[1]);
    *reinterpret_cast<__nv_bfloat162*>(h + i + 2) = __nv_bfloat162(hh[2], hh[3]);
    *reinterpret_cast<__nv_bfloat162*>(l + i)     = __nv_bfloat162(ll[0], ll[1]);
    *reinterpret_cast<__nv_bfloat162*>(l + i + 2) = __nv_bfloat162(ll[2], ll[3]);
}

// ======== layered weight transpose+split: W[l][K,N] -> Wt[l][N,K] ========
__global__ void tsplit_w(const float* __restrict__ W_, __nv_bfloat16* __restrict__ Th_,
                         __nv_bfloat16* __restrict__ Tl_, int K, int N,
                         size_t sSrc, size_t sDst)
{
    const int l = blockIdx.z;
    const float* W = W_ + (size_t)l * sSrc;
    __nv_bfloat16* Th = Th_ + (size_t)l * sDst;
    __nv_bfloat16* Tl = Tl_ + (size_t)l * sDst;

    __shared__ float tile[32][33];
    int n0 = blockIdx.x * 32, k0 = blockIdx.y * 32;
    int tx = threadIdx.x, ty = threadIdx.y;
#pragma unroll
    for (int i = 0; i < 4; i++)
        tile[ty + 8 * i][tx] = W[(size_t)(k0 + ty + 8 * i) * N + n0 + tx];
    __syncthreads();
#pragma unroll
    for (int i = 0; i < 4; i++) {
        float v = tile[tx][ty + 8 * i];
        __nv_bfloat16 hi = __float2bfloat16(v);
        __nv_bfloat16 lo = __float2bfloat16(v - __bfloat162float(hi));
        size_t o = (size_t)(n0 + ty + 8 * i) * K + k0 + tx;
        Th[o] = hi;
        Tl[o] = lo;
    }
}

// batched version (kv [P_,D_] -> kvT [D_,P_] per batch)
__global__ void tsplit_b(const float* __restrict__ W_, __nv_bfloat16* __restrict__ Th_,
                         __nv_bfloat16* __restrict__ Tl_, int K, int N)
{
    const int bz = blockIdx.z;
    const float* W = W_ + (size_t)bz * K * N;
    __nv_bfloat16* Th = Th_ + (size_t)bz * N * K;
    __nv_bfloat16* Tl = Tl_ + (size_t)bz * N * K;

    __shared__ float tile[32][33];
    int n0 = blockIdx.x * 32, k0 = blockIdx.y * 32;
    int tx = threadIdx.x, ty = threadIdx.y;
#pragma unroll
    for (int i = 0; i < 4; i++)
        tile[ty + 8 * i][tx] = W[(size_t)(k0 + ty + 8 * i) * N + n0 + tx];
    __syncthreads();
#pragma unroll
    for (int i = 0; i < 4; i++) {
        float v = tile[tx][ty + 8 * i];
        __nv_bfloat16 hi = __float2bfloat16(v);
        __nv_bfloat16 lo = __float2bfloat16(v - __bfloat162float(hi));
        size_t o = (size_t)(n0 + ty + 8 * i) * K + k0 + tx;
        Th[o] = hi;
        Tl[o] = lo;
    }
}

__global__ void pack_bias3_all(const float* __restrict__ bq, const float* __restrict__ bk,
                               const float* __restrict__ bv, float* __restrict__ b3)
{
    int i = blockIdx.x * 256 + threadIdx.x;   // over L_*3*D_
    int l = i / (3 * D_);
    int j = i % (3 * D_);
    float v;
    if (j < D_)            v = bq[l * D_ + j];
    else if (j < 2 * D_)   v = bk[l * D_ + j - D_];
    else                   v = bv[l * D_ + j - 2 * D_];
    b3[i] = v;
}

// ======== split-K (deterministic) SIMT TN GEMM ========
#define BM 64
#define BN 64
#define BK 16

__global__ void __launch_bounds__(256) gemm_tn_part(
    const float* __restrict__ A0, const float* __restrict__ B0, float* __restrict__ P0,
    int M, int N, int K, long sA, long sB)
{
    __shared__ __align__(16) float As[BK][BM + 4];
    __shared__ __align__(16) float Bs[BK][BN + 4];

    const int bz = blockIdx.z;
    const int batch  = bz / KSPL;
    const int kslice = bz % KSPL;
    const float* A  = A0 + (long)batch * sA;
    const float* Bp = B0 + (long)batch * sB;
    float* Cp = P0 + ((long)kslice * B_ + batch) * (long)M * N;

    const int kper = K / KSPL;
    const int kbeg = kslice * kper;
    const int kend = kbeg + kper;

    int m0 = blockIdx.y * BM;
    int n0 = blockIdx.x * BN;
    int tid = threadIdx.x;
    int tx = tid & 15, ty = tid >> 4;

    float acc[4][4] = {};

    for (int k0 = kbeg; k0 < kend; k0 += BK) {
#pragma unroll
        for (int e = 0; e < 4; e++) {
            int idx = tid + e * 256;
            int r = idx >> 6, c = idx & 63;
            As[r][c] = A[(long)(k0 + r) * M + (m0 + c)];
            Bs[r][c] = Bp[(long)(k0 + r) * N + (n0 + c)];
        }
        __syncthreads();
#pragma unroll
        for (int kk = 0; kk < BK; kk++) {
            float4 av = *reinterpret_cast<const float4*>(&As[kk][ty * 4]);
            float4 bv = *reinterpret_cast<const float4*>(&Bs[kk][tx * 4]);
            float a4[4] = {av.x, av.y, av.z, av.w};
            float b4[4] = {bv.x, bv.y, bv.z, bv.w};
#pragma unroll
            for (int i = 0; i < 4; i++)
#pragma unroll
                for (int j = 0; j < 4; j++)
                    acc[i][j] = fmaf(a4[i], b4[j], acc[i][j]);
        }
        __syncthreads();
    }

#pragma unroll
    for (int i = 0; i < 4; i++) {
        int m = m0 + ty * 4 + i;
#pragma unroll
        for (int j = 0; j < 4; j++)
            Cp[(long)m * N + (n0 + tx * 4 + j)] = acc[i][j];
    }
}

// reduce kv partials (fixed order)
__global__ void kv_reduce(const float* __restrict__ kvp, float* __restrict__ kv)
{
    size_t i = (size_t)blockIdx.x * 256 + threadIdx.x;
    const size_t stride = (size_t)B_ * P_ * D_;
    float s = 0.f;
#pragma unroll
    for (int ks = 0; ks < KSPL; ks++)
        s += kvp[ks * stride + i];
    kv[i] = s;
}

// -------- embedding + positional --------
__global__ void embed_k(const int* __restrict__ x, const float* __restrict__ emb,
                        const float* __restrict__ pos, float* __restrict__ h)
{
    long idx = (long)blockIdx.x * 256 + threadIdx.x;
    int  d   = (int)(idx & (D_ - 1));
    long tok = idx >> 9;
    int  s   = (int)(tok & (S_ - 1));
    int  xv  = x[tok];
    h[idx] = emb[(long)xv * D_ + d] + pos[(long)s * D_ + d];
}

// -------- ksum two-stage --------
__global__ void ksum_part(const float* __restrict__ pk, float* __restrict__ part)
{
    int b = blockIdx.x;
    int chunk = blockIdx.y;
    int p = threadIdx.x;
    const int rows = S_ / KSCH;
    const float* base = pk + (long)b * S_ * P_ + (long)chunk * rows * P_ + p;
    float s = 0.f;
#pragma unroll 8
    for (int i = 0; i < rows; i++)
        s += base[(long)i * P_];
    part[(chunk * B_ + b) * P_ + p] = s;
}

__global__ void ksum_red(const float* __restrict__ part, float* __restrict__ ks)
{
    int i = blockIdx.x * 256 + threadIdx.x;
    if (i >= B_ * P_) return;
    int b = i / P_, p = i % P_;
    float s = 0.f;
#pragma unroll
    for (int c = 0; c < KSCH; c++)
        s += part[(c * B_ + b) * P_ + p];
    ks[i] = s;
}

// -------- z --------
__global__ void z_k(const float* __restrict__ pq, const float* __restrict__ ks,
                    float* __restrict__ z)
{
    int row  = blockIdx.x * 8 + (threadIdx.x >> 5);
    int lane = threadIdx.x & 31;
    int b = row >> 12;
    const float* pr = pq + (long)row * P_;
    const float* kk = ks + b * P_;
    float s = 0.f;
#pragma unroll
    for (int i = lane; i < P_; i += 32) s += pr[i] * kk[i];
#pragma unroll
    for (int o = 16; o; o >>= 1) s += __shfl_xor_sync(0xffffffffu, s, o);
    if (!lane) z[row] = s;
}

// -------- layernorm, split output --------
__global__ void ln_split_k(const float* __restrict__ in, const float* __restrict__ g,
                           const float* __restrict__ bb,
                           __nv_bfloat16* __restrict__ oh, __nv_bfloat16* __restrict__ ol)
{
    int row = blockIdx.x;
    int t = threadIdx.x;
    const float* x = in + (long)row * D_;
    float v0 = x[t], v1 = x[t + 256];

    float s = v0 + v1;
    __shared__ float red[8];
    __shared__ float red2[8];
#pragma unroll
    for (int o = 16; o; o >>= 1) s += __shfl_xor_sync(0xffffffffu, s, o);
    if ((t & 31) == 0) red[t >> 5] = s;
    __syncthreads();
    float tot = 0.f;
#pragma unroll
    for (int w = 0; w < 8; w++) tot += red[w];
    float mean = tot * (1.0f / 512.0f);

    float d0 = v0 - mean, d1 = v1 - mean;
    float q = d0 * d0 + d1 * d1;
#pragma unroll
    for (int o = 16; o; o >>= 1) q += __shfl_xor_sync(0xffffffffu, q, o);
    if ((t & 31) == 0) red2[t >> 5] = q;
    __syncthreads();
    float tq = 0.f;
#pragma unroll
    for (int w = 0; w < 8; w++) tq += red2[w];
    float inv = rsqrtf(tq * (1.0f / 512.0f) + 1e-5f);

#pragma unroll
    for (int half = 0; half < 2; half++) {
        int d = t + half * 256;
        float dv = (half ? d1 : d0);
        float v = dv * inv * g[d] + bb[d];
        __nv_bfloat16 hi = __float2bfloat16(v);
        __nv_bfloat16 lo = __float2bfloat16(v - __bfloat162float(hi));
        oh[(long)row * D_ + d] = hi;
        ol[(long)row * D_ + d] = lo;
    }
}

// -------- mean pool two-stage --------
__global__ void pool_part(const float* __restrict__ h, float* __restrict__ part)
{
    int b = blockIdx.x;
    int chunk = blockIdx.y;
    int d = threadIdx.x;
    const int rows = S_ / PLCH;
    const float* base = h + (long)b * S_ * D_ + (long)chunk * rows * D_ + d;
    float s = 0.f;
#pragma unroll 8
    for (int i = 0; i < rows; i++)
        s += base[(long)i * D_];
    part[(chunk * B_ + b) * D_ + d] = s;
}

__global__ void pool_red(const float* __restrict__ part, float* __restrict__ pool)
{
    int i = blockIdx.x * 256 + threadIdx.x;
    if (i >= B_ * D_) return;
    int b = i / D_, d = i % D_;
    float s = 0.f;
#pragma unroll
    for (int c = 0; c < PLCH; c++)
        s += part[(c * B_ + b) * D_ + d];
    pool[i] = s * (1.0f / (float)S_);
}

__global__ void head1_k(const float* __restrict__ pool, const float* __restrict__ W,
                        const float* __restrict__ bias, float* __restrict__ h1)
{
    int b = blockIdx.x;
    int j = threadIdx.x;
    const float* p = pool + b * D_;
    float s = bias[j];
    for (int d = 0; d < D_; d++) s += p[d] * W[d * DH_ + j];
    h1[b * DH_ + j] = fmaxf(s, 0.f);
}

__global__ void head2_k(const float* __restrict__ h1, const float* __restrict__ W,
                        const float* __restrict__ bias, float* __restrict__ out)
{
    int i = threadIdx.x;
    int b = i / C_, c = i % C_;
    float s = bias[c];
    for (int d = 0; d < DH_; d++) s += h1[b * DH_ + d] * W[d * C_ + c];
    out[i] = s;
}

// -------- host orchestration --------
static float* sym_addr_f(const void* sym) {
    void* p = nullptr;
    cudaGetSymbolAddress(&p, sym);
    return (float*)p;
}
static __nv_bfloat16* sym_addr_b(const void* sym) {
    void* p = nullptr;
    cudaGetSymbolAddress(&p, sym);
    return (__nv_bfloat16*)p;
}

extern "C" void kernel_launch(void* const* d_in, const int* in_sizes, int n_in,
                              void* d_out, int out_size)
{
    const int*   x    = (const int*)d_in[0];
    const float* emb  = (const float*)d_in[1];
    const float* pos  = (const float*)d_in[2];
    const float* Wq   = (const float*)d_in[3];
    const float* bq   = (const float*)d_in[4];
    const float* Wk   = (const float*)d_in[5];
    const float* bk   = (const float*)d_in[6];
    const float* Wv   = (const float*)d_in[7];
    const float* bv   = (const float*)d_in[8];
    const float* Wf   = (const float*)d_in[9];
    const float* bf   = (const float*)d_in[10];
    const float* Wo   = (const float*)d_in[11];
    const float* bo   = (const float*)d_in[12];
    const float* lng  = (const float*)d_in[13];
    const float* lnb  = (const float*)d_in[14];
    const float* W1   = (const float*)d_in[15];
    const float* b1   = (const float*)d_in[16];
    const float* W2   = (const float*)d_in[17];
    const float* b2   = (const float*)d_in[18];
    const float* Wh1  = (const float*)d_in[19];
    const float* bh1  = (const float*)d_in[20];
    const float* Wh2  = (const float*)d_in[21];
    const float* bh2  = (const float*)d_in[22];
    float* out = (float*)d_out;

    float* h    = sym_addr_f(g_h);
    float* v    = sym_addr_f(g_v);
    float* a    = sym_addr_f(g_a);
    float* pq   = sym_addr_f(g_pq);
    float* pk   = sym_addr_f(g_pk);
    float* kv   = sym_addr_f(g_kv);
    float* kvp  = sym_addr_f(g_kvp);
    float* ksum = sym_addr_f(g_ksum);
    float* ksp  = sym_addr_f(g_kspart);
    float* z    = sym_addr_f(g_z);
    float* pool = sym_addr_f(g_pool);
    float* plp  = sym_addr_f(g_plpart);
    float* h1   = sym_addr_f(g_h1);
    float* b3   = sym_addr_f(g_bias3);

    __nv_bfloat16* hh   = sym_addr_b(g_hh);
    __nv_bfloat16* hl   = sym_addr_b(g_hl);
    __nv_bfloat16* qkvh = sym_addr_b(g_qkvh);
    __nv_bfloat16* qkvl = sym_addr_b(g_qkvl);
    __nv_bfloat16* mh   = sym_addr_b(g_mh);
    __nv_bfloat16* ml   = sym_addr_b(g_ml);
    __nv_bfloat16* pqh  = sym_addr_b(g_pqh);
    __nv_bfloat16* pql  = sym_addr_b(g_pql);
    __nv_bfloat16* kvth = sym_addr_b(g_kvth);
    __nv_bfloat16* kvtl = sym_addr_b(g_kvtl);

    __nv_bfloat16* wqkvh = sym_addr_b(g_wqkvh);
    __nv_bfloat16* wqkvl = sym_addr_b(g_wqkvl);
    __nv_bfloat16* wfh   = sym_addr_b(g_wfh);
    __nv_bfloat16* wfl   = sym_addr_b(g_wfl);
    __nv_bfloat16* woh   = sym_addr_b(g_woh);
    __nv_bfloat16* wol   = sym_addr_b(g_wol);
    __nv_bfloat16* w1h   = sym_addr_b(g_w1h);
    __nv_bfloat16* w1l   = sym_addr_b(g_w1l);
    __nv_bfloat16* w2h   = sym_addr_b(g_w2h);
    __nv_bfloat16* w2l   = sym_addr_b(g_w2l);

    cudaFuncSetAttribute(gemm_mma<EP_NONE, true,  true >, cudaFuncAttributeMaxDynamicSharedMemorySize, MMA_SMEM);
    cudaFuncSetAttribute(gemm_mma<EP_NONE, true,  false>, cudaFuncAttributeMaxDynamicSharedMemorySize, MMA_SMEM);
    cudaFuncSetAttribute(gemm_mma<EP_NONE, false, true >, cudaFuncAttributeMaxDynamicSharedMemorySize, MMA_SMEM);
    cudaFuncSetAttribute(gemm_mma<EP_GELU, false, true >, cudaFuncAttributeMaxDynamicSharedMemorySize, MMA_SMEM);
    cudaFuncSetAttribute(gemm_feat, cudaFuncAttributeMaxDynamicSharedMemorySize, MMA_SMEM);
    cudaFuncSetAttribute(gemm_zs_mma, cudaFuncAttributeMaxDynamicSharedMemorySize, MMA_SMEM);

    dim3 tsD(32, 8);

    // ---- hoisted weight preprocessing (activation-independent) ----
    embed_k<<<(BS_ * D_) / 256, 256>>>(x, emb, pos, h);
    pack_bias3_all<<<(L_ * 3 * D_) / 256, 256>>>(bq, bk, bv, b3);
    tsplit_w<<<dim3(D_ / 32, D_ / 32, L_), tsD>>>(Wq, wqkvh,                    wqkvl,                    D_, D_, (size_t)D_*D_, (size_t)3*D_*D_);
    tsplit_w<<<dim3(D_ / 32, D_ / 32, L_), tsD>>>(Wk, wqkvh + (size_t)D_*D_,    wqkvl + (size_t)D_*D_,    D_, D_, (size_t)D_*D_, (size_t)3*D_*D_);
    tsplit_w<<<dim3(D_ / 32, D_ / 32, L_), tsD>>>(Wv, wqkvh + (size_t)2*D_*D_,  wqkvl + (size_t)2*D_*D_,  D_, D_, (size_t)D_*D_, (size_t)3*D_*D_);
    tsplit_w<<<dim3(P_ / 32, D_ / 32, L_), tsD>>>(Wf, wfh, wfl, D_, P_, (size_t)D_*P_, (size_t)P_*D_);
    tsplit_w<<<dim3(D_ / 32, D_ / 32, L_), tsD>>>(Wo, woh, wol, D_, D_, (size_t)D_*D_, (size_t)D_*D_);
    tsplit_w<<<dim3(DF_ / 32, D_ / 32, L_), tsD>>>(W1, w1h, w1l, D_, DF_, (size_t)D_*DF_, (size_t)DF_*D_);
    tsplit_w<<<dim3(D_ / 32, DF_ / 32, L_), tsD>>>(W2, w2h, w2l, DF_, D_, (size_t)DF_*D_, (size_t)D_*DF_);

    split_k<<<(BS_ * D_) / 1024, 256>>>(h, hh, hl);

    for (int l = 0; l < L_; l++) {
        // ---- fused QKV: N = 1536 ----
        dim3 gQKV(3 * D_ / 128, BS_ / 128);
        gemm_mma<EP_NONE, true, true><<<gQKV, 256, MMA_SMEM>>>(
            hh, hl, D_, wqkvh + (size_t)l*3*D_*D_, wqkvl + (size_t)l*3*D_*D_, b3 + l * 3 * D_,
            v, D_, 2 * D_,
            qkvh, qkvl, 3 * D_, BS_, 3 * D_, D_);

        // ---- feature maps (merged pq + pk launch) ----
        gemm_feat<<<dim3(1, 2 * BS_ / 128), 256, MMA_SMEM>>>(
            qkvh, qkvl, wfh + (size_t)l*P_*D_, wfl + (size_t)l*P_*D_, bf + l * P_,
            pq, pk, pqh, pql);

        // ---- linear attention core ----
        ksum_part<<<dim3(B_, KSCH), P_>>>(pk, ksp);
        ksum_red<<<(B_ * P_ + 255) / 256, 256>>>(ksp, ksum);
        dim3 gKV(D_ / BN, P_ / BM, B_ * KSPL);
        gemm_tn_part<<<gKV, 256>>>(pk, v, kvp, P_, D_, S_,
                                   (long)S_ * P_, (long)S_ * D_);
        kv_reduce<<<(B_ * P_ * D_) / 256, 256>>>(kvp, kv);
        z_k<<<BS_ / 8, 256>>>(pq, ksum, z);
        tsplit_b<<<dim3(D_ / 32, P_ / 32, B_), tsD>>>(kv, kvth, kvtl, P_, D_);
        dim3 gZS(D_ / 128, S_ / 128, B_);
        gemm_zs_mma<<<gZS, 256, MMA_SMEM>>>(pqh, pql, kvth, kvtl, z, hh, hl);

        // ---- Wo ----
        dim3 gDD(D_ / 128, BS_ / 128);
        gemm_mma<EP_NONE, true, false><<<gDD, 256, MMA_SMEM>>>(
            hh, hl, D_, woh + (size_t)l*D_*D_, wol + (size_t)l*D_*D_, bo + l * D_,
            a, D_, 0, nullptr, nullptr, 0, BS_, D_, D_);

        ln_split_k<<<BS_, 256>>>(a, lng + l * D_, lnb + l * D_, hh, hl);

        // ---- MLP ----
        dim3 gW1(DF_ / 128, BS_ / 128);
        gemm_mma<EP_GELU, false, true><<<gW1, 256, MMA_SMEM>>>(
            hh, hl, D_, w1h + (size_t)l*DF_*D_, w1l + (size_t)l*DF_*D_, b1 + l * DF_,
            nullptr, 0, 0, mh, ml, DF_, BS_, DF_, D_);
        if (l == L_ - 1) {
            gemm_mma<EP_NONE, true, true><<<gDD, 256, MMA_SMEM>>>(
                mh, ml, DF_, w2h + (size_t)l*D_*DF_, w2l + (size_t)l*D_*DF_, b2 + l * D_,
                h, D_, 0, hh, hl, D_, BS_, D_, DF_);
        } else {
            gemm_mma<EP_NONE, false, true><<<gDD, 256, MMA_SMEM>>>(
                mh, ml, DF_, w2h + (size_t)l*D_*DF_, w2l + (size_t)l*D_*DF_, b2 + l * D_,
                nullptr, 0, 0, hh, hl, D_, BS_, D_, DF_);
        }
    }

    pool_part<<<dim3(B_, PLCH), D_>>>(h, plp);
    pool_red<<<(B_ * D_ + 255) / 256, 256>>>(plp, pool);
    head1_k<<<B_, DH_>>>(pool, Wh1, bh1, h1);
    head2_k<<<1, B_ * C_>>>(h1, Wh2, bh2, out);
}

// round 16
// speedup vs baseline: 1.0133x; 1.0009x over previous
#include <cuda_runtime.h>
#include <cuda_bf16.h>
#include <math.h>
#include <stdint.h>

// Problem constants
#define B_   8
#define S_   4096
#define D_   512
#define P_   128
#define L_   4
#define DF_  2048
#define DH_  256
#define C_   2
#define BS_  (B_*S_)   // 32768 tokens

#define KSPL 8         // split-K factor for kv GEMM
#define KSCH 16        // ksum chunks
#define PLCH 32        // pool chunks

// -------- scratch (device globals) --------
__device__ float g_h[(size_t)BS_*D_];
__device__ float g_v[(size_t)BS_*D_];
__device__ float g_a[(size_t)BS_*D_];
__device__ float g_pk[(size_t)BS_*P_];
__device__ float g_kvp[(size_t)KSPL*B_*P_*D_];
__device__ float g_ksum[B_*P_];
__device__ float g_kspart[KSCH*B_*P_];
__device__ float g_z[BS_];
__device__ float g_pool[B_*D_];
__device__ float g_plpart[PLCH*B_*D_];
__device__ float g_h1[B_*DH_];
__device__ float g_bias3[L_*3*D_];

// bf16 split buffers (activations)
__device__ __nv_bfloat16 g_hh[(size_t)BS_*D_];
__device__ __nv_bfloat16 g_hl[(size_t)BS_*D_];
__device__ __nv_bfloat16 g_qkvh[(size_t)BS_*3*D_];
__device__ __nv_bfloat16 g_qkvl[(size_t)BS_*3*D_];
__device__ __nv_bfloat16 g_mh[(size_t)BS_*DF_];
__device__ __nv_bfloat16 g_ml[(size_t)BS_*DF_];
__device__ __nv_bfloat16 g_pqh[(size_t)BS_*P_];
__device__ __nv_bfloat16 g_pql[(size_t)BS_*P_];
__device__ __nv_bfloat16 g_kvth[(size_t)B_*D_*P_];
__device__ __nv_bfloat16 g_kvtl[(size_t)B_*D_*P_];

// bf16 split weights (all layers, transposed [N,K] K-major), hoisted
__device__ __nv_bfloat16 g_wqkvh[(size_t)L_*3*D_*D_];
__device__ __nv_bfloat16 g_wqkvl[(size_t)L_*3*D_*D_];
__device__ __nv_bfloat16 g_wfh[(size_t)L_*P_*D_];
__device__ __nv_bfloat16 g_wfl[(size_t)L_*P_*D_];
__device__ __nv_bfloat16 g_woh[(size_t)L_*D_*D_];
__device__ __nv_bfloat16 g_wol[(size_t)L_*D_*D_];
__device__ __nv_bfloat16 g_w1h[(size_t)L_*DF_*D_];
__device__ __nv_bfloat16 g_w1l[(size_t)L_*DF_*D_];
__device__ __nv_bfloat16 g_w2h[(size_t)L_*D_*DF_];
__device__ __nv_bfloat16 g_w2l[(size_t)L_*D_*DF_];

enum { EP_NONE = 0, EP_ELU1 = 1, EP_GELU = 2 };

__device__ __forceinline__ float gelu_f(float x) {
    float x3 = x * x * x;
    float t  = tanhf(0.7978845608028654f * (x + 0.044715f * x3));
    return 0.5f * x * (1.0f + t);
}
__device__ __forceinline__ float epi_apply(float v, int EPI) {
    if (EPI == EP_ELU1) v = (v > 0.f) ? (v + 1.0f) : expf(v);
    if (EPI == EP_GELU) v = gelu_f(v);
    return v;
}

// ================= mma.sync bf16x3 GEMM, 3-stage swizzled pipeline =================
#define TILE_B  (128 * 64)         // 8192 B per operand tile
#define STAGE_B (4 * TILE_B)       // 32768 B
#define NSTAGE  3
#define MMA_SMEM (NSTAGE * STAGE_B)  // 98304

__device__ __forceinline__ uint32_t smem_u32(const void* p) {
    uint32_t a;
    asm("{ .reg .u64 t; cvta.to.shared.u64 t, %1; cvt.u32.u64 %0, t; }" : "=r"(a) : "l"(p));
    return a;
}

#define CP_ASYNC16(dst, src) \
    asm volatile("cp.async.cg.shared.global [%0], [%1], 16;" :: "r"(dst), "l"(src) : "memory")
#define CP_COMMIT() asm volatile("cp.async.commit_group;" ::: "memory")
#define CP_WAIT1()  asm volatile("cp.async.wait_group 1;" ::: "memory")
#define CP_WAIT0()  asm volatile("cp.async.wait_group 0;" ::: "memory")

#define LDSM_X4(r0,r1,r2,r3,addr) \
    asm volatile("ldmatrix.sync.aligned.m8n8.x4.shared.b16 {%0,%1,%2,%3}, [%4];" \
                 : "=r"(r0), "=r"(r1), "=r"(r2), "=r"(r3) : "r"(addr))

__device__ __forceinline__ void mma_bf16(float* c, const uint32_t* a, const uint32_t* b) {
    asm volatile(
        "mma.sync.aligned.m16n8k16.row.col.f32.bf16.bf16.f32 "
        "{%0,%1,%2,%3}, {%4,%5,%6,%7}, {%8,%9}, {%0,%1,%2,%3};"
        : "+f"(c[0]), "+f"(c[1]), "+f"(c[2]), "+f"(c[3])
        : "r"(a[0]), "r"(a[1]), "r"(a[2]), "r"(a[3]), "r"(b[0]), "r"(b[1]));
}

#define SWZ_OFF(r, c) ((uint32_t)((r) * 64 + ((((c) ^ (((r) >> 1) & 3))) << 4)))

// R13-proven mainloop body (pass-major; af reloaded from Al mid-chunk).
#define MMA_MAINLOOP_BODY(tAh, tAl, tBh, tBl, aBase, cA, sxA, bBase, cB, sxB, acc)   \
    _Pragma("unroll")                                                                \
    for (int ks = 0; ks < 2; ks++) {                                                 \
        const uint32_t acx = (uint32_t)((((ks * 2) + (cA)) ^ (sxA)) << 4);           \
        const uint32_t bcx = (uint32_t)((((ks * 2) + (cB)) ^ (sxB)) << 4);           \
        uint32_t af[4][4], bhf[4][2], blf[4][2];                                     \
        _Pragma("unroll")                                                            \
        for (int mt = 0; mt < 4; mt++)                                               \
            LDSM_X4(af[mt][0], af[mt][1], af[mt][2], af[mt][3],                      \
                    (tAh) + (aBase) + (uint32_t)(mt * 1024) + acx);                  \
        LDSM_X4(bhf[0][0], bhf[0][1], bhf[1][0], bhf[1][1], (tBh) + (bBase) + bcx);  \
        LDSM_X4(bhf[2][0], bhf[2][1], bhf[3][0], bhf[3][1],                          \
                (tBh) + (bBase) + 1024u + bcx);                                      \
        LDSM_X4(blf[0][0], blf[0][1], blf[1][0], blf[1][1], (tBl) + (bBase) + bcx);  \
        LDSM_X4(blf[2][0], blf[2][1], blf[3][0], blf[3][1],                          \
                (tBl) + (bBase) + 1024u + bcx);                                      \
        _Pragma("unroll")                                                            \
        for (int mt = 0; mt < 4; mt++)                                               \
            _Pragma("unroll")                                                        \
            for (int nt = 0; nt < 4; nt++)                                           \
                mma_bf16(acc[mt][nt], af[mt], bhf[nt]);                              \
        _Pragma("unroll")                                                            \
        for (int mt = 0; mt < 4; mt++)                                               \
            _Pragma("unroll")                                                        \
            for (int nt = 0; nt < 4; nt++)                                           \
                mma_bf16(acc[mt][nt], af[mt], blf[nt]);                              \
        _Pragma("unroll")                                                            \
        for (int mt = 0; mt < 4; mt++)                                               \
            LDSM_X4(af[mt][0], af[mt][1], af[mt][2], af[mt][3],                      \
                    (tAl) + (aBase) + (uint32_t)(mt * 1024) + acx);                  \
        _Pragma("unroll")                                                            \
        for (int mt = 0; mt < 4; mt++)                                               \
            _Pragma("unroll")                                                        \
            for (int nt = 0; nt < 4; nt++)                                           \
                mma_bf16(acc[mt][nt], af[mt], bhf[nt]);                              \
    }

template <int EPI, bool WF32, bool WSPLIT>
__global__ void __launch_bounds__(256, 2) gemm_mma(
    const __nv_bfloat16* __restrict__ Ah, const __nv_bfloat16* __restrict__ Al, int lda,
    const __nv_bfloat16* __restrict__ Bh, const __nv_bfloat16* __restrict__ Bl,
    const float* __restrict__ bias,
    float* __restrict__ Cf, int ldcf, int cf0,
    __nv_bfloat16* __restrict__ Chi, __nv_bfloat16* __restrict__ Clo, int ldc,
    int M, int N, int K)
{
    extern __shared__ __align__(1024) char smem[];
    const uint32_t sb = smem_u32(smem);

    const int tid  = threadIdx.x;
    const int wid  = tid >> 5;
    const int lane = tid & 31;
    const int wm   = wid & 1;
    const int wn   = wid >> 1;
    const int n0   = blockIdx.x * 128;
    const int m0   = blockIdx.y * 128;

    const __nv_bfloat16* gA[2] = { Ah + (size_t)m0 * lda, Al + (size_t)m0 * lda };
    const __nv_bfloat16* gB[2] = { Bh + (size_t)n0 * K,   Bl + (size_t)n0 * K };

    const int r0 = tid >> 2, cid = tid & 3;
    const uint32_t d0 = SWZ_OFF(r0, cid);
    const uint32_t d1 = SWZ_OFF(r0 + 64, cid);

    auto issue = [&](int slot, int kc) {
        const uint32_t stb = sb + (uint32_t)(slot * STAGE_B);
#pragma unroll
        for (int t = 0; t < 4; t++) {
            const __nv_bfloat16* src = ((t < 2) ? gA[t] : gB[t - 2]) + kc;
            const int ld = (t < 2) ? lda : K;
            uint32_t tb = stb + t * TILE_B;
            CP_ASYNC16(tb + d0, (const void*)(src + (size_t)r0 * ld + cid * 8));
            CP_ASYNC16(tb + d1, (const void*)(src + (size_t)(r0 + 64) * ld + cid * 8));
        }
        CP_COMMIT();
    };

    const int nch = K >> 5;
    float acc[4][4][4] = {};

    issue(0, 0);
    issue(1, 32);

    const int aro = (lane & 7) | (((lane >> 3) & 1) << 3);
    const int cA  = lane >> 4;
    const int sxA = (aro >> 1) & 3;
    const uint32_t aBase = (uint32_t)((wm * 64 + aro) * 64);
    const int bro = (lane & 7) | (((lane >> 4) & 1) << 3);
    const int cB  = (lane >> 3) & 1;
    const int sxB = (bro >> 1) & 3;
    const uint32_t bBase = (uint32_t)((wn * 32 + bro) * 64);

    for (int c = 0; c < nch; c++) {
        if (c + 1 < nch) CP_WAIT1(); else CP_WAIT0();
        __syncthreads();
        if (c + 2 < nch) issue((c + 2) % NSTAGE, (c + 2) << 5);

        const uint32_t stb = sb + (uint32_t)((c % NSTAGE) * STAGE_B);
        const uint32_t tAh = stb, tAl = stb + TILE_B, tBh = stb + 2 * TILE_B, tBl = stb + 3 * TILE_B;

        MMA_MAINLOOP_BODY(tAh, tAl, tBh, tBl, aBase, cA, sxA, bBase, cB, sxB, acc)
    }

#pragma unroll
    for (int mt = 0; mt < 4; mt++) {
        const int gm0 = m0 + wm * 64 + mt * 16 + (lane >> 2);
#pragma unroll
        for (int nt = 0; nt < 4; nt++) {
            const int gn = n0 + wn * 32 + nt * 8 + (lane & 3) * 2;
            const float b0v = bias[gn], b1v = bias[gn + 1];
#pragma unroll
            for (int half = 0; half < 2; half++) {
                const int gm = gm0 + half * 8;
                float v0 = epi_apply(acc[mt][nt][half*2 + 0] + b0v, EPI);
                float v1 = epi_apply(acc[mt][nt][half*2 + 1] + b1v, EPI);
                if (WF32) {
                    if (cf0 == 0 || gn >= cf0)
                        *reinterpret_cast<float2*>(Cf + (size_t)gm * ldcf + (gn - cf0)) = make_float2(v0, v1);
                }
                if (WSPLIT) {
                    __nv_bfloat16 h0 = __float2bfloat16(v0);
                    __nv_bfloat16 h1 = __float2bfloat16(v1);
                    __nv_bfloat16 l0 = __float2bfloat16(v0 - __bfloat162float(h0));
                    __nv_bfloat16 l1 = __float2bfloat16(v1 - __bfloat162float(h1));
                    *reinterpret_cast<__nv_bfloat162*>(Chi + (size_t)gm * ldc + gn) = __nv_bfloat162(h0, h1);
                    *reinterpret_cast<__nv_bfloat162*>(Clo + (size_t)gm * ldc + gn) = __nv_bfloat162(l0, l1);
                }
            }
        }
    }
}

// ===== merged feature-map GEMM: first grid half -> pq split only, second -> pk fp32 =====
__global__ void __launch_bounds__(256, 2) gemm_feat(
    const __nv_bfloat16* __restrict__ qkvh, const __nv_bfloat16* __restrict__ qkvl,
    const __nv_bfloat16* __restrict__ Bh, const __nv_bfloat16* __restrict__ Bl,
    const float* __restrict__ bias,
    float* __restrict__ pk,
    __nv_bfloat16* __restrict__ pqh, __nv_bfloat16* __restrict__ pql)
{
    extern __shared__ __align__(1024) char smem[];
    const uint32_t sb = smem_u32(smem);

    const int tid  = threadIdx.x;
    const int wid  = tid >> 5;
    const int lane = tid & 31;
    const int wm   = wid & 1;
    const int wn   = wid >> 1;
    const int half_g = (int)(gridDim.y >> 1);
    const bool isQ = ((int)blockIdx.y) < half_g;
    const int m0   = (isQ ? (int)blockIdx.y : (int)blockIdx.y - half_g) * 128;
    const int lda  = 3 * D_;
    const int K    = D_;

    const __nv_bfloat16* gA[2] = { qkvh + (isQ ? 0 : D_) + (size_t)m0 * lda,
                                   qkvl + (isQ ? 0 : D_) + (size_t)m0 * lda };
    const __nv_bfloat16* gB[2] = { Bh, Bl };

    const int r0 = tid >> 2, cid = tid & 3;
    const uint32_t d0 = SWZ_OFF(r0, cid);
    const uint32_t d1 = SWZ_OFF(r0 + 64, cid);

    auto issue = [&](int slot, int kc) {
        const uint32_t stb = sb + (uint32_t)(slot * STAGE_B);
#pragma unroll
        for (int t = 0; t < 4; t++) {
            const __nv_bfloat16* src = ((t < 2) ? gA[t] : gB[t - 2]) + kc;
            const int ld = (t < 2) ? lda : K;
            uint32_t tb = stb + t * TILE_B;
            CP_ASYNC16(tb + d0, (const void*)(src + (size_t)r0 * ld + cid * 8));
            CP_ASYNC16(tb + d1, (const void*)(src + (size_t)(r0 + 64) * ld + cid * 8));
        }
        CP_COMMIT();
    };

    const int nch = K >> 5;
    float acc[4][4][4] = {};

    issue(0, 0);
    issue(1, 32);

    const int aro = (lane & 7) | (((lane >> 3) & 1) << 3);
    const int cA  = lane >> 4;
    const int sxA = (aro >> 1) & 3;
    const uint32_t aBase = (uint32_t)((wm * 64 + aro) * 64);
    const int bro = (lane & 7) | (((lane >> 4) & 1) << 3);
    const int cB  = (lane >> 3) & 1;
    const int sxB = (bro >> 1) & 3;
    const uint32_t bBase = (uint32_t)((wn * 32 + bro) * 64);

    for (int c = 0; c < nch; c++) {
        if (c + 1 < nch) CP_WAIT1(); else CP_WAIT0();
        __syncthreads();
        if (c + 2 < nch) issue((c + 2) % NSTAGE, (c + 2) << 5);

        const uint32_t stb = sb + (uint32_t)((c % NSTAGE) * STAGE_B);
        const uint32_t tAh = stb, tAl = stb + TILE_B, tBh = stb + 2 * TILE_B, tBl = stb + 3 * TILE_B;

        MMA_MAINLOOP_BODY(tAh, tAl, tBh, tBl, aBase, cA, sxA, bBase, cB, sxB, acc)
    }

#pragma unroll
    for (int mt = 0; mt < 4; mt++) {
        const int gm0 = m0 + wm * 64 + mt * 16 + (lane >> 2);
#pragma unroll
        for (int nt = 0; nt < 4; nt++) {
            const int gn = wn * 32 + nt * 8 + (lane & 3) * 2;
            const float b0v = bias[gn], b1v = bias[gn + 1];
#pragma unroll
            for (int half = 0; half < 2; half++) {
                const int gm = gm0 + half * 8;
                float v0 = epi_apply(acc[mt][nt][half*2 + 0] + b0v, EP_ELU1);
                float v1 = epi_apply(acc[mt][nt][half*2 + 1] + b1v, EP_ELU1);
                if (isQ) {
                    __nv_bfloat16 h0 = __float2bfloat16(v0);
                    __nv_bfloat16 h1 = __float2bfloat16(v1);
                    __nv_bfloat16 l0 = __float2bfloat16(v0 - __bfloat162float(h0));
                    __nv_bfloat16 l1 = __float2bfloat16(v1 - __bfloat162float(h1));
                    *reinterpret_cast<__nv_bfloat162*>(pqh + (size_t)gm * P_ + gn) = __nv_bfloat162(h0, h1);
                    *reinterpret_cast<__nv_bfloat162*>(pql + (size_t)gm * P_ + gn) = __nv_bfloat162(l0, l1);
                } else {
                    *reinterpret_cast<float2*>(pk + (size_t)gm * P_ + gn) = make_float2(v0, v1);
                }
            }
        }
    }
}

// ===== batched zscale GEMM =====
__global__ void __launch_bounds__(256, 2) gemm_zs_mma(
    const __nv_bfloat16* __restrict__ Ah_, const __nv_bfloat16* __restrict__ Al_,
    const __nv_bfloat16* __restrict__ Bh_, const __nv_bfloat16* __restrict__ Bl_,
    const float* __restrict__ zr_,
    __nv_bfloat16* __restrict__ Chi_, __nv_bfloat16* __restrict__ Clo_)
{
    extern __shared__ __align__(1024) char smem[];
    const uint32_t sb = smem_u32(smem);

    const int bz = blockIdx.z;
    const __nv_bfloat16* Ah = Ah_ + (size_t)bz * S_ * P_;
    const __nv_bfloat16* Al = Al_ + (size_t)bz * S_ * P_;
    const __nv_bfloat16* Bh = Bh_ + (size_t)bz * D_ * P_;
    const __nv_bfloat16* Bl = Bl_ + (size_t)bz * D_ * P_;
    const float* zr = zr_ + (size_t)bz * S_;
    __nv_bfloat16* Chi = Chi_ + (size_t)bz * S_ * D_;
    __nv_bfloat16* Clo = Clo_ + (size_t)bz * S_ * D_;

    const int tid  = threadIdx.x;
    const int wid  = tid >> 5;
    const int lane = tid & 31;
    const int wm   = wid & 1;
    const int wn   = wid >> 1;
    const int n0   = blockIdx.x * 128;
    const int m0   = blockIdx.y * 128;

    const __nv_bfloat16* gA[2] = { Ah + (size_t)m0 * P_, Al + (size_t)m0 * P_ };
    const __nv_bfloat16* gB[2] = { Bh + (size_t)n0 * P_, Bl + (size_t)n0 * P_ };

    const int r0 = tid >> 2, cid = tid & 3;
    const uint32_t d0 = SWZ_OFF(r0, cid);
    const uint32_t d1 = SWZ_OFF(r0 + 64, cid);

    auto issue = [&](int slot, int kc) {
        const uint32_t stb = sb + (uint32_t)(slot * STAGE_B);
#pragma unroll
        for (int t = 0; t < 4; t++) {
            const __nv_bfloat16* src = ((t < 2) ? gA[t] : gB[t - 2]) + kc;
            uint32_t tb = stb + t * TILE_B;
            CP_ASYNC16(tb + d0, (const void*)(src + (size_t)r0 * P_ + cid * 8));
            CP_ASYNC16(tb + d1, (const void*)(src + (size_t)(r0 + 64) * P_ + cid * 8));
        }
        CP_COMMIT();
    };

    const int nch = P_ >> 5;
    float acc[4][4][4] = {};

    issue(0, 0);
    issue(1, 32);

    const int aro = (lane & 7) | (((lane >> 3) & 1) << 3);
    const int cA  = lane >> 4;
    const int sxA = (aro >> 1) & 3;
    const uint32_t aBase = (uint32_t)((wm * 64 + aro) * 64);
    const int bro = (lane & 7) | (((lane >> 4) & 1) << 3);
    const int cB  = (lane >> 3) & 1;
    const int sxB = (bro >> 1) & 3;
    const uint32_t bBase = (uint32_t)((wn * 32 + bro) * 64);

    for (int c = 0; c < nch; c++) {
        if (c + 1 < nch) CP_WAIT1(); else CP_WAIT0();
        __syncthreads();
        if (c + 2 < nch) issue((c + 2) % NSTAGE, (c + 2) << 5);

        const uint32_t stb = sb + (uint32_t)((c % NSTAGE) * STAGE_B);
        const uint32_t tAh = stb, tAl = stb + TILE_B, tBh = stb + 2 * TILE_B, tBl = stb + 3 * TILE_B;

        MMA_MAINLOOP_BODY(tAh, tAl, tBh, tBl, aBase, cA, sxA, bBase, cB, sxB, acc)
    }

#pragma unroll
    for (int mt = 0; mt < 4; mt++) {
        const int gm0 = m0 + wm * 64 + mt * 16 + (lane >> 2);
#pragma unroll
        for (int half = 0; half < 2; half++) {
            const int gm = gm0 + half * 8;
            const float zs = 1.0f / (zr[gm] + 1e-6f);
#pragma unroll
            for (int nt = 0; nt < 4; nt++) {
                const int gn = n0 + wn * 32 + nt * 8 + (lane & 3) * 2;
                float v0 = acc[mt][nt][half*2 + 0] * zs;
                float v1 = acc[mt][nt][half*2 + 1] * zs;
                __nv_bfloat16 h0 = __float2bfloat16(v0);
                __nv_bfloat16 h1 = __float2bfloat16(v1);
                __nv_bfloat16 l0 = __float2bfloat16(v0 - __bfloat162float(h0));
                __nv_bfloat16 l1 = __float2bfloat16(v1 - __bfloat162float(h1));
                *reinterpret_cast<__nv_bfloat162*>(Chi + (size_t)gm * D_ + gn) = __nv_bfloat162(h0, h1);
                *reinterpret_cast<__nv_bfloat162*>(Clo + (size_t)gm * D_ + gn) = __nv_bfloat162(l0, l1);
            }
        }
    }
}

// ======== fp32 -> (hi, lo) bf16 split ========
__global__ void split_k(const float* __restrict__ x, __nv_bfloat16* __restrict__ h,
                        __nv_bfloat16* __restrict__ l)
{
    size_t i = ((size_t)blockIdx.x * 256 + threadIdx.x) * 4;
    float4 v = *reinterpret_cast<const float4*>(x + i);
    float vv[4] = {v.x, v.y, v.z, v.w};
    __nv_bfloat16 hh[4], ll[4];
#pragma unroll
    for (int j = 0; j < 4; j++) {
        hh[j] = __float2bfloat16(vv[j]);
        ll[j] = __float2bfloat16(vv[j] - __bfloat162float(hh[j]));
    }
    *reinterpret_cast<__nv_bfloat162*>(h + i)     = __nv_bfloat162(hh[0], hh[1]);
    *reinterpret_cast<__nv_bfloat162*>(h + i + 2) = __nv_bfloat162(hh[2], hh[3]);
    *reinterpret_cast<__nv_bfloat162*>(l + i)     = __nv_bfloat162(ll[0], ll[1]);
    *reinterpret_cast<__nv_bfloat162*>(l + i + 2) = __nv_bfloat162(ll[2], ll[3]);
}

// ======== layered weight transpose+split: W[l][K,N] -> Wt[l][N,K] ========
__global__ void tsplit_w(const float* __restrict__ W_, __nv_bfloat16* __restrict__ Th_,
                         __nv_bfloat16* __restrict__ Tl_, int K, int N,
                         size_t sSrc, size_t sDst)
{
    const int l = blockIdx.z;
    const float* W = W_ + (size_t)l * sSrc;
    __nv_bfloat16* Th = Th_ + (size_t)l * sDst;
    __nv_bfloat16* Tl = Tl_ + (size_t)l * sDst;

    __shared__ float tile[32][33];
    int n0 = blockIdx.x * 32, k0 = blockIdx.y * 32;
    int tx = threadIdx.x, ty = threadIdx.y;
#pragma unroll
    for (int i = 0; i < 4; i++)
        tile[ty + 8 * i][tx] = W[(size_t)(k0 + ty + 8 * i) * N + n0 + tx];
    __syncthreads();
#pragma unroll
    for (int i = 0; i < 4; i++) {
        float v = tile[tx][ty + 8 * i];
        __nv_bfloat16 hi = __float2bfloat16(v);
        __nv_bfloat16 lo = __float2bfloat16(v - __bfloat162float(hi));
        size_t o = (size_t)(n0 + ty + 8 * i) * K + k0 + tx;
        Th[o] = hi;
        Tl[o] = lo;
    }
}

// ======== merged kv reduce + transpose + split ========
// kvp[ks][b][P,D] -> kvth/kvtl [b][D,P]
__global__ void kv_red_t(const float* __restrict__ kvp, __nv_bfloat16* __restrict__ Th_,
                         __nv_bfloat16* __restrict__ Tl_)
{
    const int bz = blockIdx.z;
    const float* base = kvp + (size_t)bz * P_ * D_;
    __nv_bfloat16* Th = Th_ + (size_t)bz * D_ * P_;
    __nv_bfloat16* Tl = Tl_ + (size_t)bz * D_ * P_;

    __shared__ float tile[32][33];
    int n0 = blockIdx.x * 32, k0 = blockIdx.y * 32;   // n = D dim, k = P dim
    int tx = threadIdx.x, ty = threadIdx.y;
    const size_t stride = (size_t)B_ * P_ * D_;
#pragma unroll
    for (int i = 0; i < 4; i++) {
        size_t off = (size_t)(k0 + ty + 8 * i) * D_ + n0 + tx;
        float s = 0.f;
#pragma unroll
        for (int ks = 0; ks < KSPL; ks++)
            s += base[ks * stride + off];
        tile[ty + 8 * i][tx] = s;
    }
    __syncthreads();
#pragma unroll
    for (int i = 0; i < 4; i++) {
        float v = tile[tx][ty + 8 * i];
        __nv_bfloat16 hi = __float2bfloat16(v);
        __nv_bfloat16 lo = __float2bfloat16(v - __bfloat162float(hi));
        size_t o = (size_t)(n0 + ty + 8 * i) * P_ + k0 + tx;
        Th[o] = hi;
        Tl[o] = lo;
    }
}

__global__ void pack_bias3_all(const float* __restrict__ bq, const float* __restrict__ bk,
                               const float* __restrict__ bv, float* __restrict__ b3)
{
    int i = blockIdx.x * 256 + threadIdx.x;
    int l = i / (3 * D_);
    int j = i % (3 * D_);
    float v;
    if (j < D_)            v = bq[l * D_ + j];
    else if (j < 2 * D_)   v = bk[l * D_ + j - D_];
    else                   v = bv[l * D_ + j - 2 * D_];
    b3[i] = v;
}

// ======== split-K (deterministic) SIMT TN GEMM ========
#define BM 64
#define BN 64
#define BK 16

__global__ void __launch_bounds__(256) gemm_tn_part(
    const float* __restrict__ A0, const float* __restrict__ B0, float* __restrict__ P0,
    int M, int N, int K, long sA, long sB)
{
    __shared__ __align__(16) float As[BK][BM + 4];
    __shared__ __align__(16) float Bs[BK][BN + 4];

    const int bz = blockIdx.z;
    const int batch  = bz / KSPL;
    const int kslice = bz % KSPL;
    const float* A  = A0 + (long)batch * sA;
    const float* Bp = B0 + (long)batch * sB;
    float* Cp = P0 + ((long)kslice * B_ + batch) * (long)M * N;

    const int kper = K / KSPL;
    const int kbeg = kslice * kper;
    const int kend = kbeg + kper;

    int m0 = blockIdx.y * BM;
    int n0 = blockIdx.x * BN;
    int tid = threadIdx.x;
    int tx = tid & 15, ty = tid >> 4;

    float acc[4][4] = {};

    for (int k0 = kbeg; k0 < kend; k0 += BK) {
#pragma unroll
        for (int e = 0; e < 4; e++) {
            int idx = tid + e * 256;
            int r = idx >> 6, c = idx & 63;
            As[r][c] = A[(long)(k0 + r) * M + (m0 + c)];
            Bs[r][c] = Bp[(long)(k0 + r) * N + (n0 + c)];
        }
        __syncthreads();
#pragma unroll
        for (int kk = 0; kk < BK; kk++) {
            float4 av = *reinterpret_cast<const float4*>(&As[kk][ty * 4]);
            float4 bv = *reinterpret_cast<const float4*>(&Bs[kk][tx * 4]);
            float a4[4] = {av.x, av.y, av.z, av.w};
            float b4[4] = {bv.x, bv.y, bv.z, bv.w};
#pragma unroll
            for (int i = 0; i < 4; i++)
#pragma unroll
                for (int j = 0; j < 4; j++)
                    acc[i][j] = fmaf(a4[i], b4[j], acc[i][j]);
        }
        __syncthreads();
    }

#pragma unroll
    for (int i = 0; i < 4; i++) {
        int m = m0 + ty * 4 + i;
#pragma unroll
        for (int j = 0; j < 4; j++)
            Cp[(long)m * N + (n0 + tx * 4 + j)] = acc[i][j];
    }
}

// -------- embedding + positional --------
__global__ void embed_k(const int* __restrict__ x, const float* __restrict__ emb,
                        const float* __restrict__ pos, float* __restrict__ h)
{
    long idx = (long)blockIdx.x * 256 + threadIdx.x;
    int  d   = (int)(idx & (D_ - 1));
    long tok = idx >> 9;
    int  s   = (int)(tok & (S_ - 1));
    int  xv  = x[tok];
    h[idx] = emb[(long)xv * D_ + d] + pos[(long)s * D_ + d];
}

// -------- ksum two-stage --------
__global__ void ksum_part(const float* __restrict__ pk, float* __restrict__ part)
{
    int b = blockIdx.x;
    int chunk = blockIdx.y;
    int p = threadIdx.x;
    const int rows = S_ / KSCH;
    const float* base = pk + (long)b * S_ * P_ + (long)chunk * rows * P_ + p;
    float s = 0.f;
#pragma unroll 8
    for (int i = 0; i < rows; i++)
        s += base[(long)i * P_];
    part[(chunk * B_ + b) * P_ + p] = s;
}

__global__ void ksum_red(const float* __restrict__ part, float* __restrict__ ks)
{
    int i = blockIdx.x * 256 + threadIdx.x;
    if (i >= B_ * P_) return;
    int b = i / P_, p = i % P_;
    float s = 0.f;
#pragma unroll
    for (int c = 0; c < KSCH; c++)
        s += part[(c * B_ + b) * P_ + p];
    ks[i] = s;
}

// -------- z from split pq --------
__global__ void z_k(const __nv_bfloat16* __restrict__ pqh, const __nv_bfloat16* __restrict__ pql,
                    const float* __restrict__ ks, float* __restrict__ z)
{
    int row  = blockIdx.x * 8 + (threadIdx.x >> 5);
    int lane = threadIdx.x & 31;
    int b = row >> 12;
    const __nv_bfloat16* ph = pqh + (long)row * P_;
    const __nv_bfloat16* pl = pql + (long)row * P_;
    const float* kk = ks + b * P_;
    float s = 0.f;
#pragma unroll
    for (int i = lane; i < P_; i += 32)
        s += (__bfloat162float(ph[i]) + __bfloat162float(pl[i])) * kk[i];
#pragma unroll
    for (int o = 16; o; o >>= 1) s += __shfl_xor_sync(0xffffffffu, s, o);
    if (!lane) z[row] = s;
}

// -------- layernorm, split output --------
__global__ void ln_split_k(const float* __restrict__ in, const float* __restrict__ g,
                           const float* __restrict__ bb,
                           __nv_bfloat16* __restrict__ oh, __nv_bfloat16* __restrict__ ol)
{
    int row = blockIdx.x;
    int t = threadIdx.x;
    const float* x = in + (long)row * D_;
    float v0 = x[t], v1 = x[t + 256];

    float s = v0 + v1;
    __shared__ float red[8];
    __shared__ float red2[8];
#pragma unroll
    for (int o = 16; o; o >>= 1) s += __shfl_xor_sync(0xffffffffu, s, o);
    if ((t & 31) == 0) red[t >> 5] = s;
    __syncthreads();
    float tot = 0.f;
#pragma unroll
    for (int w = 0; w < 8; w++) tot += red[w];
    float mean = tot * (1.0f / 512.0f);

    float d0 = v0 - mean, d1 = v1 - mean;
    float q = d0 * d0 + d1 * d1;
#pragma unroll
    for (int o = 16; o; o >>= 1) q += __shfl_xor_sync(0xffffffffu, q, o);
    if ((t & 31) == 0) red2[t >> 5] = q;
    __syncthreads();
    float tq = 0.f;
#pragma unroll
    for (int w = 0; w < 8; w++) tq += red2[w];
    float inv = rsqrtf(tq * (1.0f / 512.0f) + 1e-5f);

#pragma unroll
    for (int half = 0; half < 2; half++) {
        int d = t + half * 256;
        float dv = (half ? d1 : d0);
        float v = dv * inv * g[d] + bb[d];
        __nv_bfloat16 hi = __float2bfloat16(v);
        __nv_bfloat16 lo = __float2bfloat16(v - __bfloat162float(hi));
        oh[(long)row * D_ + d] = hi;
        ol[(long)row * D_ + d] = lo;
    }
}

// -------- mean pool two-stage --------
__global__ void pool_part(const float* __restrict__ h, float* __restrict__ part)
{
    int b = blockIdx.x;
    int chunk = blockIdx.y;
    int d = threadIdx.x;
    const int rows = S_ / PLCH;
    const float* base = h + (long)b * S_ * D_ + (long)chunk * rows * D_ + d;
    float s = 0.f;
#pragma unroll 8
    for (int i = 0; i < rows; i++)
        s += base[(long)i * D_];
    part[(chunk * B_ + b) * D_ + d] = s;
}

__global__ void pool_red(const float* __restrict__ part, float* __restrict__ pool)
{
    int i = blockIdx.x * 256 + threadIdx.x;
    if (i >= B_ * D_) return;
    int b = i / D_, d = i % D_;
    float s = 0.f;
#pragma unroll
    for (int c = 0; c < PLCH; c++)
        s += part[(c * B_ + b) * D_ + d];
    pool[i] = s * (1.0f / (float)S_);
}

__global__ void head1_k(const float* __restrict__ pool, const float* __restrict__ W,
                        const float* __restrict__ bias, float* __restrict__ h1)
{
    int b = blockIdx.x;
    int j = threadIdx.x;
    const float* p = pool + b * D_;
    float s = bias[j];
    for (int d = 0; d < D_; d++) s += p[d] * W[d * DH_ + j];
    h1[b * DH_ + j] = fmaxf(s, 0.f);
}

__global__ void head2_k(const float* __restrict__ h1, const float* __restrict__ W,
                        const float* __restrict__ bias, float* __restrict__ out)
{
    int i = threadIdx.x;
    int b = i / C_, c = i % C_;
    float s = bias[c];
    for (int d = 0; d < DH_; d++) s += h1[b * DH_ + d] * W[d * C_ + c];
    out[i] = s;
}

// -------- host orchestration --------
static float* sym_addr_f(const void* sym) {
    void* p = nullptr;
    cudaGetSymbolAddress(&p, sym);
    return (float*)p;
}
static __nv_bfloat16* sym_addr_b(const void* sym) {
    void* p = nullptr;
    cudaGetSymbolAddress(&p, sym);
    return (__nv_bfloat16*)p;
}

extern "C" void kernel_launch(void* const* d_in, const int* in_sizes, int n_in,
                              void* d_out, int out_size)
{
    const int*   x    = (const int*)d_in[0];
    const float* emb  = (const float*)d_in[1];
    const float* pos  = (const float*)d_in[2];
    const float* Wq   = (const float*)d_in[3];
    const float* bq   = (const float*)d_in[4];
    const float* Wk   = (const float*)d_in[5];
    const float* bk   = (const float*)d_in[6];
    const float* Wv   = (const float*)d_in[7];
    const float* bv   = (const float*)d_in[8];
    const float* Wf   = (const float*)d_in[9];
    const float* bf   = (const float*)d_in[10];
    const float* Wo   = (const float*)d_in[11];
    const float* bo   = (const float*)d_in[12];
    const float* lng  = (const float*)d_in[13];
    const float* lnb  = (const float*)d_in[14];
    const float* W1   = (const float*)d_in[15];
    const float* b1   = (const float*)d_in[16];
    const float* W2   = (const float*)d_in[17];
    const float* b2   = (const float*)d_in[18];
    const float* Wh1  = (const float*)d_in[19];
    const float* bh1  = (const float*)d_in[20];
    const float* Wh2  = (const float*)d_in[21];
    const float* bh2  = (const float*)d_in[22];
    float* out = (float*)d_out;

    float* h    = sym_addr_f(g_h);
    float* v    = sym_addr_f(g_v);
    float* a    = sym_addr_f(g_a);
    float* pk   = sym_addr_f(g_pk);
    float* kvp  = sym_addr_f(g_kvp);
    float* ksum = sym_addr_f(g_ksum);
    float* ksp  = sym_addr_f(g_kspart);
    float* z    = sym_addr_f(g_z);
    float* pool = sym_addr_f(g_pool);
    float* plp  = sym_addr_f(g_plpart);
    float* h1   = sym_addr_f(g_h1);
    float* b3   = sym_addr_f(g_bias3);

    __nv_bfloat16* hh   = sym_addr_b(g_hh);
    __nv_bfloat16* hl   = sym_addr_b(g_hl);
    __nv_bfloat16* qkvh = sym_addr_b(g_qkvh);
    __nv_bfloat16* qkvl = sym_addr_b(g_qkvl);
    __nv_bfloat16* mh   = sym_addr_b(g_mh);
    __nv_bfloat16* ml   = sym_addr_b(g_ml);
    __nv_bfloat16* pqh  = sym_addr_b(g_pqh);
    __nv_bfloat16* pql  = sym_addr_b(g_pql);
    __nv_bfloat16* kvth = sym_addr_b(g_kvth);
    __nv_bfloat16* kvtl = sym_addr_b(g_kvtl);

    __nv_bfloat16* wqkvh = sym_addr_b(g_wqkvh);
    __nv_bfloat16* wqkvl = sym_addr_b(g_wqkvl);
    __nv_bfloat16* wfh   = sym_addr_b(g_wfh);
    __nv_bfloat16* wfl   = sym_addr_b(g_wfl);
    __nv_bfloat16* woh   = sym_addr_b(g_woh);
    __nv_bfloat16* wol   = sym_addr_b(g_wol);
    __nv_bfloat16* w1h   = sym_addr_b(g_w1h);
    __nv_bfloat16* w1l   = sym_addr_b(g_w1l);
    __nv_bfloat16* w2h   = sym_addr_b(g_w2h);
    __nv_bfloat16* w2l   = sym_addr_b(g_w2l);

    cudaFuncSetAttribute(gemm_mma<EP_NONE, true,  true >, cudaFuncAttributeMaxDynamicSharedMemorySize, MMA_SMEM);
    cudaFuncSetAttribute(gemm_mma<EP_NONE, true,  false>, cudaFuncAttributeMaxDynamicSharedMemorySize, MMA_SMEM);
    cudaFuncSetAttribute(gemm_mma<EP_NONE, false, true >, cudaFuncAttributeMaxDynamicSharedMemorySize, MMA_SMEM);
    cudaFuncSetAttribute(gemm_mma<EP_GELU, false, true >, cudaFuncAttributeMaxDynamicSharedMemorySize, MMA_SMEM);
    cudaFuncSetAttribute(gemm_feat, cudaFuncAttributeMaxDynamicSharedMemorySize, MMA_SMEM);
    cudaFuncSetAttribute(gemm_zs_mma, cudaFuncAttributeMaxDynamicSharedMemorySize, MMA_SMEM);

    dim3 tsD(32, 8);

    // ---- hoisted weight preprocessing (activation-independent) ----
    embed_k<<<(BS_ * D_) / 256, 256>>>(x, emb, pos, h);
    pack_bias3_all<<<(L_ * 3 * D_) / 256, 256>>>(bq, bk, bv, b3);
    tsplit_w<<<dim3(D_ / 32, D_ / 32, L_), tsD>>>(Wq, wqkvh,                    wqkvl,                    D_, D_, (size_t)D_*D_, (size_t)3*D_*D_);
    tsplit_w<<<dim3(D_ / 32, D_ / 32, L_), tsD>>>(Wk, wqkvh + (size_t)D_*D_,    wqkvl + (size_t)D_*D_,    D_, D_, (size_t)D_*D_, (size_t)3*D_*D_);
    tsplit_w<<<dim3(D_ / 32, D_ / 32, L_), tsD>>>(Wv, wqkvh + (size_t)2*D_*D_,  wqkvl + (size_t)2*D_*D_,  D_, D_, (size_t)D_*D_, (size_t)3*D_*D_);
    tsplit_w<<<dim3(P_ / 32, D_ / 32, L_), tsD>>>(Wf, wfh, wfl, D_, P_, (size_t)D_*P_, (size_t)P_*D_);
    tsplit_w<<<dim3(D_ / 32, D_ / 32, L_), tsD>>>(Wo, woh, wol, D_, D_, (size_t)D_*D_, (size_t)D_*D_);
    tsplit_w<<<dim3(DF_ / 32, D_ / 32, L_), tsD>>>(W1, w1h, w1l, D_, DF_, (size_t)D_*DF_, (size_t)DF_*D_);
    tsplit_w<<<dim3(D_ / 32, DF_ / 32, L_), tsD>>>(W2, w2h, w2l, DF_, D_, (size_t)DF_*D_, (size_t)D_*DF_);

    split_k<<<(BS_ * D_) / 1024, 256>>>(h, hh, hl);

    for (int l = 0; l < L_; l++) {
        // ---- fused QKV: N = 1536 ----
        dim3 gQKV(3 * D_ / 128, BS_ / 128);
        gemm_mma<EP_NONE, true, true><<<gQKV, 256, MMA_SMEM>>>(
            hh, hl, D_, wqkvh + (size_t)l*3*D_*D_, wqkvl + (size_t)l*3*D_*D_, b3 + l * 3 * D_,
            v, D_, 2 * D_,
            qkvh, qkvl, 3 * D_, BS_, 3 * D_, D_);

        // ---- feature maps (merged pq + pk launch; pq split only, pk fp32 only) ----
        gemm_feat<<<dim3(1, 2 * BS_ / 128), 256, MMA_SMEM>>>(
            qkvh, qkvl, wfh + (size_t)l*P_*D_, wfl + (size_t)l*P_*D_, bf + l * P_,
            pk, pqh, pql);

        // ---- linear attention core ----
        ksum_part<<<dim3(B_, KSCH), P_>>>(pk, ksp);
        ksum_red<<<(B_ * P_ + 255) / 256, 256>>>(ksp, ksum);
        dim3 gKV(D_ / BN, P_ / BM, B_ * KSPL);
        gemm_tn_part<<<gKV, 256>>>(pk, v, kvp, P_, D_, S_,
                                   (long)S_ * P_, (long)S_ * D_);
        z_k<<<BS_ / 8, 256>>>(pqh, pql, ksum, z);
        kv_red_t<<<dim3(D_ / 32, P_ / 32, B_), tsD>>>(kvp, kvth, kvtl);
        dim3 gZS(D_ / 128, S_ / 128, B_);
        gemm_zs_mma<<<gZS, 256, MMA_SMEM>>>(pqh, pql, kvth, kvtl, z, hh, hl);

        // ---- Wo ----
        dim3 gDD(D_ / 128, BS_ / 128);
        gemm_mma<EP_NONE, true, false><<<gDD, 256, MMA_SMEM>>>(
            hh, hl, D_, woh + (size_t)l*D_*D_, wol + (size_t)l*D_*D_, bo + l * D_,
            a, D_, 0, nullptr, nullptr, 0, BS_, D_, D_);

        ln_split_k<<<BS_, 256>>>(a, lng + l * D_, lnb + l * D_, hh, hl);

        // ---- MLP ----
        dim3 gW1(DF_ / 128, BS_ / 128);
        gemm_mma<EP_GELU, false, true><<<gW1, 256, MMA_SMEM>>>(
            hh, hl, D_, w1h + (size_t)l*DF_*D_, w1l + (size_t)l*DF_*D_, b1 + l * DF_,
            nullptr, 0, 0, mh, ml, DF_, BS_, DF_, D_);
        if (l == L_ - 1) {
            gemm_mma<EP_NONE, true, true><<<gDD, 256, MMA_SMEM>>>(
                mh, ml, DF_, w2h + (size_t)l*D_*DF_, w2l + (size_t)l*D_*DF_, b2 + l * D_,
                h, D_, 0, hh, hl, D_, BS_, D_, DF_);
        } else {
            gemm_mma<EP_NONE, false, true><<<gDD, 256, MMA_SMEM>>>(
                mh, ml, DF_, w2h + (size_t)l*D_*DF_, w2l + (size_t)l*D_*DF_, b2 + l * D_,
                nullptr, 0, 0, hh, hl, D_, BS_, D_, DF_);
        }
    }

    pool_part<<<dim3(B_, PLCH), D_>>>(h, plp);
    pool_red<<<(B_ * D_ + 255) / 256, 256>>>(plp, pool);
    head1_k<<<B_, DH_>>>(pool, Wh1, bh1, h1);
    head2_k<<<1, B_ * C_>>>(h1, Wh2, bh2, out);
}